// round 5
// baseline (speedup 1.0000x reference)
#include <cuda_runtime.h>
#include <math.h>
#include <stdint.h>

// Problem constants
#define Bz 8
#define Tz 1024
#define Cz 768
#define NHz 12
#define HDz 64
#define Mz (Bz*Tz)        // 8192

// Scratch (device globals; no allocation)
__device__ float g_q[Bz*NHz*Tz*HDz];
__device__ float g_k[Bz*NHz*Tz*HDz];
__device__ float g_v[Bz*NHz*Tz*HDz];
__device__ float g_y[Bz*Tz*Cz];

__device__ __forceinline__ uint32_t f2tf32(float f) {
    uint32_t u;
    asm("cvt.rna.tf32.f32 %0, %1;" : "=r"(u) : "f"(f));
    return u;
}

__device__ __forceinline__ void mma_tf32(
    float& d0, float& d1, float& d2, float& d3,
    uint32_t a0, uint32_t a1, uint32_t a2, uint32_t a3,
    uint32_t b0, uint32_t b1)
{
    asm volatile(
        "mma.sync.aligned.m16n8k8.row.col.f32.tf32.tf32.f32 "
        "{%0,%1,%2,%3}, {%4,%5,%6,%7}, {%8,%9}, {%0,%1,%2,%3};\n"
        : "+f"(d0), "+f"(d1), "+f"(d2), "+f"(d3)
        : "r"(a0), "r"(a1), "r"(a2), "r"(a3), "r"(b0), "r"(b1));
}

__device__ __forceinline__ void cp16(uint32_t smem_dst, const float* gsrc) {
    asm volatile("cp.async.cg.shared.global [%0], [%1], 16;\n"
                 :: "r"(smem_dst), "l"(gsrc));
}
#define CP_COMMIT() asm volatile("cp.async.commit_group;\n" ::: "memory")
#define CP_WAIT(n)  asm volatile("cp.async.wait_group %0;\n" :: "n"(n) : "memory")

// ---------------------------------------------------------------------------
// TF32 GEMM v3: 128x128 CTA tile, K-stage 32, cp.async double-buffered,
// conflict-free smem strides (A:36, B:264), tf32 convert at fragment load.
// 8 warps (wm 0..1, wn 0..3), warp tile 64x32.
// ---------------------------------------------------------------------------
#define ASTR 36
#define BSTR 264
#define KSTG 32
#define A_WORDS (128*ASTR)   // per buffer
#define B_WORDS (KSTG*BSTR)  // per buffer

template <int EPI>
__global__ __launch_bounds__(256) void tgemm_kernel(
    const float* __restrict__ A, const float* __restrict__ Bm,
    const float* __restrict__ bias, float* __restrict__ Cout,
    int M, int N, int K)
{
    extern __shared__ float gsm[];
    float* As = gsm;                 // [2][A_WORDS]
    float* Bs = gsm + 2*A_WORDS;     // [2][B_WORDS]

    const int tid  = threadIdx.x;
    const int wid  = tid >> 5;
    const int lane = tid & 31;
    const int wm   = wid & 1;
    const int wn   = wid >> 1;
    const int gr   = lane >> 2;
    const int tig  = lane & 3;
    const int bm   = blockIdx.y * 128;
    const int bn   = blockIdx.x * 128;

    // cp.async geometry: A stage 128x32 f32, B stage 32x128 f32
    const int ar = tid >> 1;              // 0..127
    const int ac = (tid & 1) * 16;        // 0 / 16 (float offset)
    const int bk = tid >> 3;              // 0..31
    const int bc = (tid & 7) * 16;        // 0..112

    const float* Asrc = A + (size_t)(bm + ar) * K + ac;
    const float* Bsrc = Bm + (size_t)bk * N + bn + bc;

    uint32_t a_smem_base, b_smem_base;
    {
        uint64_t t0 = __cvta_generic_to_shared(As + ar*ASTR + ac);
        uint64_t t1 = __cvta_generic_to_shared(Bs + bk*BSTR + bc);
        a_smem_base = (uint32_t)t0;
        b_smem_base = (uint32_t)t1;
    }

    float acc[4][4][4];
#pragma unroll
    for (int i = 0; i < 4; ++i)
#pragma unroll
        for (int j = 0; j < 4; ++j)
#pragma unroll
            for (int r = 0; r < 4; ++r) acc[i][j][r] = 0.f;

    const int nstages = K / KSTG;

    // Prologue: stage 0 -> buf 0
    {
        const float* as = Asrc;
        const float* bs = Bsrc;
#pragma unroll
        for (int j = 0; j < 4; ++j)
            cp16(a_smem_base + j*16, as + j*4);
#pragma unroll
        for (int j = 0; j < 4; ++j)
            cp16(b_smem_base + j*16, bs + j*4);
        CP_COMMIT();
    }

    for (int s = 0; s < nstages; ++s) {
        const int buf = s & 1;
        const bool more = (s + 1 < nstages);

        if (more) {
            const float* as = Asrc + (s + 1) * KSTG;
            const float* bs = Bsrc + (size_t)(s + 1) * KSTG * N;
            const uint32_t ad = a_smem_base + (buf ^ 1) * (A_WORDS * 4);
            const uint32_t bd = b_smem_base + (buf ^ 1) * (B_WORDS * 4);
#pragma unroll
            for (int j = 0; j < 4; ++j)
                cp16(ad + j*16, as + j*4);
#pragma unroll
            for (int j = 0; j < 4; ++j)
                cp16(bd + j*16, bs + j*4);
            CP_COMMIT();
            CP_WAIT(1);          // stage s resident
        } else {
            CP_WAIT(0);
        }
        __syncthreads();

        const float* Asb = As + buf * A_WORDS;
        const float* Bsb = Bs + buf * B_WORDS;

#pragma unroll
        for (int ks = 0; ks < 4; ++ks) {
            const int kb = ks * 8;
            uint32_t af[4][4];
#pragma unroll
            for (int mt = 0; mt < 4; ++mt) {
                const int r = wm*64 + mt*16 + gr;
                af[mt][0] = f2tf32(Asb[ r     *ASTR + kb + tig    ]);
                af[mt][1] = f2tf32(Asb[(r + 8)*ASTR + kb + tig    ]);
                af[mt][2] = f2tf32(Asb[ r     *ASTR + kb + tig + 4]);
                af[mt][3] = f2tf32(Asb[(r + 8)*ASTR + kb + tig + 4]);
            }
            uint32_t bf[4][2];
#pragma unroll
            for (int nt = 0; nt < 4; ++nt) {
                const int n = wn*32 + nt*8 + gr;
                bf[nt][0] = f2tf32(Bsb[(kb + tig    )*BSTR + n]);
                bf[nt][1] = f2tf32(Bsb[(kb + tig + 4)*BSTR + n]);
            }
#pragma unroll
            for (int mt = 0; mt < 4; ++mt)
#pragma unroll
                for (int nt = 0; nt < 4; ++nt)
                    mma_tf32(acc[mt][nt][0], acc[mt][nt][1],
                             acc[mt][nt][2], acc[mt][nt][3],
                             af[mt][0], af[mt][1], af[mt][2], af[mt][3],
                             bf[nt][0], bf[nt][1]);
        }
        __syncthreads();   // all warps done with buf before it is refilled
    }

    // Epilogue (unchanged)
#pragma unroll
    for (int mt = 0; mt < 4; ++mt) {
#pragma unroll
        for (int nt = 0; nt < 4; ++nt) {
            const int nb2 = bn + wn*32 + nt*8 + 2*tig;
#pragma unroll
            for (int half = 0; half < 2; ++half) {
                const int m = bm + wm*64 + mt*16 + gr + half*8;
                const float v0 = acc[mt][nt][half*2 + 0] + bias[nb2 + 0];
                const float v1 = acc[mt][nt][half*2 + 1] + bias[nb2 + 1];
                if (EPI == 0) {
                    const int which = nb2 / Cz;
                    const int c = nb2 - which * Cz;
                    const int h = c >> 6;
                    const int d = c & 63;
                    const int b = m >> 10;
                    const int t = m & 1023;
                    float* dst = (which == 0) ? g_q : (which == 1) ? g_k : g_v;
                    float2 val = make_float2(v0, v1);
                    *(float2*)&dst[(((size_t)(b*NHz + h) << 10) + t)*HDz + d] = val;
                } else {
                    float2 val = make_float2(v0, v1);
                    *(float2*)&Cout[(size_t)m*N + nb2] = val;
                }
            }
        }
    }
}

// ---------------------------------------------------------------------------
// Flash attention v2 (unchanged from R4): 128 q/CTA, register softmax.
// ---------------------------------------------------------------------------
#define KSx 68
#define TILE_WORDS (64*KSx)

__global__ __launch_bounds__(256) void flash2_kernel(
    const float* __restrict__ gq, const float* __restrict__ gk,
    const float* __restrict__ gv, float* __restrict__ gy)
{
    extern __shared__ uint32_t smu[];
    uint32_t* Kbuf = smu;
    uint32_t* Vbuf = smu + 2*TILE_WORDS;

    const int bh  = blockIdx.x;
    const int qb  = 7 - blockIdx.y;
    const int tid = threadIdx.x;
    const int wid = tid >> 5, lane = tid & 31;
    const int gr  = lane >> 2;
    const int tig = lane & 3;

    const int qrow0 = qb*128 + wid*16;
    const float scale = 0.125f;

    const float* qbase = gq + ((size_t)bh*Tz + qrow0) * HDz;
    uint32_t qf[8][4];
#pragma unroll
    for (int kb = 0; kb < 8; ++kb) {
        qf[kb][0] = f2tf32(qbase[(size_t)(gr    )*HDz + kb*8 + tig    ]);
        qf[kb][1] = f2tf32(qbase[(size_t)(gr + 8)*HDz + kb*8 + tig    ]);
        qf[kb][2] = f2tf32(qbase[(size_t)(gr    )*HDz + kb*8 + tig + 4]);
        qf[kb][3] = f2tf32(qbase[(size_t)(gr + 8)*HDz + kb*8 + tig + 4]);
    }

    float O[8][4];
#pragma unroll
    for (int nt = 0; nt < 8; ++nt)
#pragma unroll
        for (int r = 0; r < 4; ++r) O[nt][r] = 0.f;
    float m0 = -INFINITY, m1 = -INFINITY, l0 = 0.f, l1 = 0.f;

    const int ntiles = 2*qb + 2;

    const int sr = tid >> 2;
    const int sc = (tid & 3) * 16;
    const float* kbase0 = gk + (size_t)bh*Tz*HDz;
    const float* vbase0 = gv + (size_t)bh*Tz*HDz;

    {
        const float* kp = kbase0 + (size_t)sr*HDz + sc;
        const float* vp = vbase0 + (size_t)sr*HDz + sc;
        uint32_t* Kd = Kbuf;
        uint32_t* Vd = Vbuf;
#pragma unroll
        for (int j = 0; j < 4; ++j) {
            float4 k4 = *(const float4*)(kp + j*4);
            uint4 ku = make_uint4(f2tf32(k4.x), f2tf32(k4.y),
                                  f2tf32(k4.z), f2tf32(k4.w));
            *(uint4*)&Kd[sr*KSx + sc + j*4] = ku;
            float4 v4 = *(const float4*)(vp + j*4);
            Vd[(sc + j*4 + 0)*KSx + sr] = f2tf32(v4.x);
            Vd[(sc + j*4 + 1)*KSx + sr] = f2tf32(v4.y);
            Vd[(sc + j*4 + 2)*KSx + sr] = f2tf32(v4.z);
            Vd[(sc + j*4 + 3)*KSx + sr] = f2tf32(v4.w);
        }
    }
    __syncthreads();

    const int srcA = (lane & ~3) | (tig >> 1);
    const int srcB = srcA + 2;

    for (int kt = 0; kt < ntiles; ++kt) {
        const int cur = kt & 1;
        const bool more = (kt + 1 < ntiles);

        float4 kx[4], vx[4];
        if (more) {
            const float* kp = kbase0 + ((size_t)(kt+1)*64 + sr)*HDz + sc;
            const float* vp = vbase0 + ((size_t)(kt+1)*64 + sr)*HDz + sc;
#pragma unroll
            for (int j = 0; j < 4; ++j) {
                kx[j] = *(const float4*)(kp + j*4);
                vx[j] = *(const float4*)(vp + j*4);
            }
        }

        if (kt*64 <= qrow0 + 15) {
            const uint32_t* Ksb = Kbuf + cur*TILE_WORDS;
            const uint32_t* Vsb = Vbuf + cur*TILE_WORDS;

            float sacc[8][4];
#pragma unroll
            for (int nt = 0; nt < 8; ++nt)
#pragma unroll
                for (int r = 0; r < 4; ++r) sacc[nt][r] = 0.f;

#pragma unroll
            for (int kb = 0; kb < 8; ++kb) {
#pragma unroll
                for (int nt = 0; nt < 8; ++nt) {
                    uint32_t b0 = Ksb[(nt*8 + gr)*KSx + kb*8 + tig    ];
                    uint32_t b1 = Ksb[(nt*8 + gr)*KSx + kb*8 + tig + 4];
                    mma_tf32(sacc[nt][0], sacc[nt][1], sacc[nt][2], sacc[nt][3],
                             qf[kb][0], qf[kb][1], qf[kb][2], qf[kb][3],
                             b0, b1);
                }
            }

            const bool bnd = (kt*64 + 63 > qrow0);
            if (bnd) {
                const int r0 = qrow0 + gr, r1 = qrow0 + gr + 8;
#pragma unroll
                for (int nt = 0; nt < 8; ++nt) {
                    const int c0 = kt*64 + nt*8 + 2*tig;
                    sacc[nt][0] = (c0     > r0) ? -1e30f : sacc[nt][0]*scale;
                    sacc[nt][1] = (c0 + 1 > r0) ? -1e30f : sacc[nt][1]*scale;
                    sacc[nt][2] = (c0     > r1) ? -1e30f : sacc[nt][2]*scale;
                    sacc[nt][3] = (c0 + 1 > r1) ? -1e30f : sacc[nt][3]*scale;
                }
            } else {
#pragma unroll
                for (int nt = 0; nt < 8; ++nt)
#pragma unroll
                    for (int r = 0; r < 4; ++r) sacc[nt][r] *= scale;
            }

            float mx0 = -INFINITY, mx1 = -INFINITY;
#pragma unroll
            for (int nt = 0; nt < 8; ++nt) {
                mx0 = fmaxf(mx0, fmaxf(sacc[nt][0], sacc[nt][1]));
                mx1 = fmaxf(mx1, fmaxf(sacc[nt][2], sacc[nt][3]));
            }
            mx0 = fmaxf(mx0, __shfl_xor_sync(0xffffffffu, mx0, 1));
            mx0 = fmaxf(mx0, __shfl_xor_sync(0xffffffffu, mx0, 2));
            mx1 = fmaxf(mx1, __shfl_xor_sync(0xffffffffu, mx1, 1));
            mx1 = fmaxf(mx1, __shfl_xor_sync(0xffffffffu, mx1, 2));

            const float mn0 = fmaxf(m0, mx0);
            const float mn1 = fmaxf(m1, mx1);
            const float a0 = __expf(m0 - mn0);
            const float a1 = __expf(m1 - mn1);
            m0 = mn0; m1 = mn1;

            float s0 = 0.f, s1 = 0.f;
#pragma unroll
            for (int nt = 0; nt < 8; ++nt) {
                sacc[nt][0] = __expf(sacc[nt][0] - mn0);
                sacc[nt][1] = __expf(sacc[nt][1] - mn0);
                sacc[nt][2] = __expf(sacc[nt][2] - mn1);
                sacc[nt][3] = __expf(sacc[nt][3] - mn1);
                s0 += sacc[nt][0] + sacc[nt][1];
                s1 += sacc[nt][2] + sacc[nt][3];
            }
            s0 += __shfl_xor_sync(0xffffffffu, s0, 1);
            s0 += __shfl_xor_sync(0xffffffffu, s0, 2);
            s1 += __shfl_xor_sync(0xffffffffu, s1, 1);
            s1 += __shfl_xor_sync(0xffffffffu, s1, 2);
            l0 = l0*a0 + s0;
            l1 = l1*a1 + s1;

#pragma unroll
            for (int nt = 0; nt < 8; ++nt) {
                O[nt][0] *= a0;  O[nt][1] *= a0;
                O[nt][2] *= a1;  O[nt][3] *= a1;
            }

#pragma unroll
            for (int nt = 0; nt < 8; ++nt)
#pragma unroll
                for (int r = 0; r < 4; ++r)
                    sacc[nt][r] = __uint_as_float(f2tf32(sacc[nt][r]));

#pragma unroll
            for (int kb = 0; kb < 8; ++kb) {
                float e, o;
                e = __shfl_sync(0xffffffffu, sacc[kb][0], srcA);
                o = __shfl_sync(0xffffffffu, sacc[kb][1], srcA);
                const uint32_t pa0 = __float_as_uint((tig & 1) ? o : e);
                e = __shfl_sync(0xffffffffu, sacc[kb][2], srcA);
                o = __shfl_sync(0xffffffffu, sacc[kb][3], srcA);
                const uint32_t pa1 = __float_as_uint((tig & 1) ? o : e);
                e = __shfl_sync(0xffffffffu, sacc[kb][0], srcB);
                o = __shfl_sync(0xffffffffu, sacc[kb][1], srcB);
                const uint32_t pa2 = __float_as_uint((tig & 1) ? o : e);
                e = __shfl_sync(0xffffffffu, sacc[kb][2], srcB);
                o = __shfl_sync(0xffffffffu, sacc[kb][3], srcB);
                const uint32_t pa3 = __float_as_uint((tig & 1) ? o : e);

#pragma unroll
                for (int nt = 0; nt < 8; ++nt) {
                    uint32_t b0 = Vsb[(nt*8 + gr)*KSx + kb*8 + tig    ];
                    uint32_t b1 = Vsb[(nt*8 + gr)*KSx + kb*8 + tig + 4];
                    mma_tf32(O[nt][0], O[nt][1], O[nt][2], O[nt][3],
                             pa0, pa1, pa2, pa3, b0, b1);
                }
            }
        }

        __syncthreads();
        if (more) {
            const int nb = cur ^ 1;
            uint32_t* Kd = Kbuf + nb*TILE_WORDS;
            uint32_t* Vd = Vbuf + nb*TILE_WORDS;
#pragma unroll
            for (int j = 0; j < 4; ++j) {
                uint4 ku = make_uint4(f2tf32(kx[j].x), f2tf32(kx[j].y),
                                      f2tf32(kx[j].z), f2tf32(kx[j].w));
                *(uint4*)&Kd[sr*KSx + sc + j*4] = ku;
                Vd[(sc + j*4 + 0)*KSx + sr] = f2tf32(vx[j].x);
                Vd[(sc + j*4 + 1)*KSx + sr] = f2tf32(vx[j].y);
                Vd[(sc + j*4 + 2)*KSx + sr] = f2tf32(vx[j].z);
                Vd[(sc + j*4 + 3)*KSx + sr] = f2tf32(vx[j].w);
            }
            __syncthreads();
        }
    }

    const int b = bh / NHz;
    const int h = bh % NHz;
    const float inv0 = 1.f / l0;
    const float inv1 = 1.f / l1;
    const int q0 = qrow0 + gr;
#pragma unroll
    for (int nt = 0; nt < 8; ++nt) {
        const int col = nt*8 + 2*tig;
        float2 w0 = make_float2(O[nt][0]*inv0, O[nt][1]*inv0);
        float2 w1 = make_float2(O[nt][2]*inv1, O[nt][3]*inv1);
        *(float2*)&gy[((size_t)b*Tz + q0    )*Cz + h*HDz + col] = w0;
        *(float2*)&gy[((size_t)b*Tz + q0 + 8)*Cz + h*HDz + col] = w1;
    }
}

// ---------------------------------------------------------------------------
extern "C" void kernel_launch(void* const* d_in, const int* in_sizes, int n_in,
                              void* d_out, int out_size)
{
    (void)in_sizes; (void)n_in; (void)out_size;
    const float* x      = (const float*)d_in[0];
    const float* w_attn = (const float*)d_in[1];
    const float* b_attn = (const float*)d_in[2];
    const float* w_proj = (const float*)d_in[3];
    const float* b_proj = (const float*)d_in[4];
    float* out = (float*)d_out;

    float *pq, *pk, *pv, *py;
    cudaGetSymbolAddress((void**)&pq, g_q);
    cudaGetSymbolAddress((void**)&pk, g_k);
    cudaGetSymbolAddress((void**)&pv, g_v);
    cudaGetSymbolAddress((void**)&py, g_y);

    const int gemm_smem = (2*A_WORDS + 2*B_WORDS) * (int)sizeof(float); // 104,448 B
    cudaFuncSetAttribute(tgemm_kernel<0>,
                         cudaFuncAttributeMaxDynamicSharedMemorySize, gemm_smem);
    cudaFuncSetAttribute(tgemm_kernel<1>,
                         cudaFuncAttributeMaxDynamicSharedMemorySize, gemm_smem);

    const int flash_smem = 4 * TILE_WORDS * (int)sizeof(uint32_t);  // 69,632 B
    cudaFuncSetAttribute(flash2_kernel,
                         cudaFuncAttributeMaxDynamicSharedMemorySize, flash_smem);

    // 1) QKV = x @ w_attn + b_attn (tf32 + cp.async), scatter to g_q/g_k/g_v
    {
        dim3 grid(3*Cz/128, Mz/128);
        tgemm_kernel<0><<<grid, 256, gemm_smem>>>(x, w_attn, b_attn, nullptr,
                                                  Mz, 3*Cz, Cz);
    }
    // 2) Flash attention v2 into g_y
    {
        dim3 grid(Bz*NHz, Tz/128);
        flash2_kernel<<<grid, 256, flash_smem>>>(pq, pk, pv, py);
    }
    // 3) out = g_y @ w_proj + b_proj (tf32 + cp.async)
    {
        dim3 grid(Cz/128, Mz/128);
        tgemm_kernel<1><<<grid, 256, gemm_smem>>>(py, w_proj, b_proj, out,
                                                  Mz, Cz, Cz);
    }
}

// round 6
// speedup vs baseline: 1.2613x; 1.2613x over previous
#include <cuda_runtime.h>
#include <math.h>
#include <stdint.h>

// Problem constants
#define Bz 8
#define Tz 1024
#define Cz 768
#define NHz 12
#define HDz 64
#define Mz (Bz*Tz)        // 8192

// Scratch (device globals; no allocation)
__device__ float g_q[Bz*NHz*Tz*HDz];
__device__ float g_k[Bz*NHz*Tz*HDz];
__device__ float g_v[Bz*NHz*Tz*HDz];
__device__ float g_y[Bz*Tz*Cz];

__device__ __forceinline__ uint32_t f2tf32(float f) {
    uint32_t u;
    asm("cvt.rna.tf32.f32 %0, %1;" : "=r"(u) : "f"(f));
    return u;
}

__device__ __forceinline__ void mma_tf32(
    float& d0, float& d1, float& d2, float& d3,
    uint32_t a0, uint32_t a1, uint32_t a2, uint32_t a3,
    uint32_t b0, uint32_t b1)
{
    asm volatile(
        "mma.sync.aligned.m16n8k8.row.col.f32.tf32.tf32.f32 "
        "{%0,%1,%2,%3}, {%4,%5,%6,%7}, {%8,%9}, {%0,%1,%2,%3};\n"
        : "+f"(d0), "+f"(d1), "+f"(d2), "+f"(d3)
        : "r"(a0), "r"(a1), "r"(a2), "r"(a3), "r"(b0), "r"(b1));
}

// ---------------------------------------------------------------------------
// TF32 GEMM v4: 128x128 CTA tile, K-stage 16, LDG->reg->cvt->STS staging
// (keeps L1 reuse), FRAGMENT-MAJOR smem layout:
//   A tiles: T = (mtile 0..7)*2 + ks; word off = T*132 + (lane^((lane>>3)&3))*4 + w
//            (w: 0=a0(gr,tig) 1=a1(gr+8,tig) 2=a2(gr,tig+4) 3=a3(gr+8,tig+4))
//   B tiles: T2 = ks*16 + ntile(0..15); word off = T2*66 + lane*2 + w (w=khalf)
// Consumer: 4x LDS.128 (A) + 4x LDS.64 (B) per k-step. One sync per stage.
// ---------------------------------------------------------------------------
#define AFW 2112   // 16 tiles * 132
#define BFW 2112   // 32 tiles * 66

template <int EPI>
__global__ __launch_bounds__(256) void tgemm_kernel(
    const float* __restrict__ A, const float* __restrict__ Bm,
    const float* __restrict__ bias, float* __restrict__ Cout,
    int M, int N, int K)
{
    __shared__ __align__(16) uint32_t Afr[2][AFW];
    __shared__ __align__(16) uint32_t Bfr[2][BFW];

    const int tid  = threadIdx.x;
    const int wid  = tid >> 5;
    const int lane = tid & 31;
    const int wm   = wid & 1;
    const int wn   = wid >> 1;
    const int gr   = lane >> 2;
    const int tig  = lane & 3;
    const int bm   = blockIdx.y * 128;
    const int bn   = blockIdx.x * 128;

    // ---- Producer geometry ----
    // A: rows ar0 and ar0+64, k = k0..k0+3
    const int ar0 = tid >> 2;            // 0..63
    const int k0  = (tid & 3) * 4;       // 0,4,8,12
    const int pks = k0 >> 3;
    const int pkh = (k0 >> 2) & 1;
    const int agr = ar0 & 7;             // same for ar0+64
    const int ag2 = (agr >> 1) & 3;
    const int awb0 = ((ar0      >> 4)*2 + pks)*132 + agr*16 + pkh*2 + ((ar0 >> 3) & 1);
    const int awb1 = (((ar0+64) >> 4)*2 + pks)*132 + agr*16 + pkh*2 + (((ar0+64) >> 3) & 1);
    // B: k rows bk and bk+8, n = bn0..bn0+3
    const int bk   = tid >> 5;           // 0..7
    const int bn0  = (tid & 31) * 4;
    const int btig = bk & 3;
    const int bkh  = (bk >> 2) & 1;
    const int bcom = (bn0 >> 3)*66 + ((bn0 & 7)*4 + btig)*2 + bkh;
    const int bwb0 = bcom;               // ks = 0
    const int bwb1 = 16*66 + bcom;       // ks = 1

    const float* Ap0 = A + (size_t)(bm + ar0)      * K + k0;
    const float* Ap1 = A + (size_t)(bm + ar0 + 64) * K + k0;
    const float* Bp0 = Bm + (size_t)bk       * N + bn + bn0;
    const float* Bp1 = Bm + (size_t)(bk + 8) * N + bn + bn0;

    // ---- Consumer geometry ----
    const int aswz  = (lane ^ ((lane >> 3) & 3)) * 4;
    const int boff2 = lane * 2;

    float acc[4][4][4];
#pragma unroll
    for (int i = 0; i < 4; ++i)
#pragma unroll
        for (int j = 0; j < 4; ++j)
#pragma unroll
            for (int r = 0; r < 4; ++r) acc[i][j][r] = 0.f;

    const int nstages = K / 16;

    // ---- Prologue: stage 0 -> buf 0 ----
    {
        float4 a0 = *(const float4*)(Ap0);
        float4 a1 = *(const float4*)(Ap1);
        float4 b0 = *(const float4*)(Bp0);
        float4 b1 = *(const float4*)(Bp1);
        uint32_t* Au = Afr[0];
        uint32_t* Bu = Bfr[0];
        Au[awb0 + ((0^ag2)<<2)] = f2tf32(a0.x);
        Au[awb0 + ((1^ag2)<<2)] = f2tf32(a0.y);
        Au[awb0 + ((2^ag2)<<2)] = f2tf32(a0.z);
        Au[awb0 + ((3^ag2)<<2)] = f2tf32(a0.w);
        Au[awb1 + ((0^ag2)<<2)] = f2tf32(a1.x);
        Au[awb1 + ((1^ag2)<<2)] = f2tf32(a1.y);
        Au[awb1 + ((2^ag2)<<2)] = f2tf32(a1.z);
        Au[awb1 + ((3^ag2)<<2)] = f2tf32(a1.w);
        Bu[bwb0     ] = f2tf32(b0.x);
        Bu[bwb0 +  8] = f2tf32(b0.y);
        Bu[bwb0 + 16] = f2tf32(b0.z);
        Bu[bwb0 + 24] = f2tf32(b0.w);
        Bu[bwb1     ] = f2tf32(b1.x);
        Bu[bwb1 +  8] = f2tf32(b1.y);
        Bu[bwb1 + 16] = f2tf32(b1.z);
        Bu[bwb1 + 24] = f2tf32(b1.w);
    }
    __syncthreads();

    for (int s = 0; s < nstages; ++s) {
        const int buf = s & 1;
        const bool more = (s + 1 < nstages);

        float4 a0, a1, b0, b1;
        if (more) {
            const int ko = (s + 1) * 16;
            a0 = *(const float4*)(Ap0 + ko);
            a1 = *(const float4*)(Ap1 + ko);
            b0 = *(const float4*)(Bp0 + (size_t)ko * N);
            b1 = *(const float4*)(Bp1 + (size_t)ko * N);
        }

        // ---- Consume buf ----
        const uint32_t* Af = Afr[buf];
        const uint32_t* Bf = Bfr[buf];
#pragma unroll
        for (int ks = 0; ks < 2; ++ks) {
            uint4 af[4];
#pragma unroll
            for (int mt = 0; mt < 4; ++mt)
                af[mt] = *(const uint4*)&Af[((wm*4 + mt)*2 + ks)*132 + aswz];
            uint2 bf[4];
#pragma unroll
            for (int nt = 0; nt < 4; ++nt)
                bf[nt] = *(const uint2*)&Bf[(ks*16 + wn*4 + nt)*66 + boff2];
#pragma unroll
            for (int mt = 0; mt < 4; ++mt)
#pragma unroll
                for (int nt = 0; nt < 4; ++nt)
                    mma_tf32(acc[mt][nt][0], acc[mt][nt][1],
                             acc[mt][nt][2], acc[mt][nt][3],
                             af[mt].x, af[mt].y, af[mt].z, af[mt].w,
                             bf[nt].x, bf[nt].y);
        }

        // ---- Produce buf^1 (read last in stage s-1; guarded by prior sync) ----
        if (more) {
            uint32_t* Au = Afr[buf ^ 1];
            uint32_t* Bu = Bfr[buf ^ 1];
            Au[awb0 + ((0^ag2)<<2)] = f2tf32(a0.x);
            Au[awb0 + ((1^ag2)<<2)] = f2tf32(a0.y);
            Au[awb0 + ((2^ag2)<<2)] = f2tf32(a0.z);
            Au[awb0 + ((3^ag2)<<2)] = f2tf32(a0.w);
            Au[awb1 + ((0^ag2)<<2)] = f2tf32(a1.x);
            Au[awb1 + ((1^ag2)<<2)] = f2tf32(a1.y);
            Au[awb1 + ((2^ag2)<<2)] = f2tf32(a1.z);
            Au[awb1 + ((3^ag2)<<2)] = f2tf32(a1.w);
            Bu[bwb0     ] = f2tf32(b0.x);
            Bu[bwb0 +  8] = f2tf32(b0.y);
            Bu[bwb0 + 16] = f2tf32(b0.z);
            Bu[bwb0 + 24] = f2tf32(b0.w);
            Bu[bwb1     ] = f2tf32(b1.x);
            Bu[bwb1 +  8] = f2tf32(b1.y);
            Bu[bwb1 + 16] = f2tf32(b1.z);
            Bu[bwb1 + 24] = f2tf32(b1.w);
        }
        __syncthreads();   // one barrier per stage
    }

    // ---- Epilogue (unchanged numerics) ----
#pragma unroll
    for (int mt = 0; mt < 4; ++mt) {
#pragma unroll
        for (int nt = 0; nt < 4; ++nt) {
            const int nb2 = bn + wn*32 + nt*8 + 2*tig;
#pragma unroll
            for (int half = 0; half < 2; ++half) {
                const int m = bm + wm*64 + mt*16 + gr + half*8;
                const float v0 = acc[mt][nt][half*2 + 0] + bias[nb2 + 0];
                const float v1 = acc[mt][nt][half*2 + 1] + bias[nb2 + 1];
                if (EPI == 0) {
                    const int which = nb2 / Cz;
                    const int c = nb2 - which * Cz;
                    const int h = c >> 6;
                    const int d = c & 63;
                    const int b = m >> 10;
                    const int t = m & 1023;
                    float* dst = (which == 0) ? g_q : (which == 1) ? g_k : g_v;
                    float2 val = make_float2(v0, v1);
                    *(float2*)&dst[(((size_t)(b*NHz + h) << 10) + t)*HDz + d] = val;
                } else {
                    float2 val = make_float2(v0, v1);
                    *(float2*)&Cout[(size_t)m*N + nb2] = val;
                }
            }
        }
    }
}

// ---------------------------------------------------------------------------
// Flash attention v2 (R4 numerics), now single __syncthreads per k-tile.
// ---------------------------------------------------------------------------
#define KSx 68
#define TILE_WORDS (64*KSx)

__global__ __launch_bounds__(256) void flash2_kernel(
    const float* __restrict__ gq, const float* __restrict__ gk,
    const float* __restrict__ gv, float* __restrict__ gy)
{
    extern __shared__ uint32_t smu[];
    uint32_t* Kbuf = smu;
    uint32_t* Vbuf = smu + 2*TILE_WORDS;

    const int bh  = blockIdx.x;
    const int qb  = 7 - blockIdx.y;
    const int tid = threadIdx.x;
    const int wid = tid >> 5, lane = tid & 31;
    const int gr  = lane >> 2;
    const int tig = lane & 3;

    const int qrow0 = qb*128 + wid*16;
    const float scale = 0.125f;

    const float* qbase = gq + ((size_t)bh*Tz + qrow0) * HDz;
    uint32_t qf[8][4];
#pragma unroll
    for (int kb = 0; kb < 8; ++kb) {
        qf[kb][0] = f2tf32(qbase[(size_t)(gr    )*HDz + kb*8 + tig    ]);
        qf[kb][1] = f2tf32(qbase[(size_t)(gr + 8)*HDz + kb*8 + tig    ]);
        qf[kb][2] = f2tf32(qbase[(size_t)(gr    )*HDz + kb*8 + tig + 4]);
        qf[kb][3] = f2tf32(qbase[(size_t)(gr + 8)*HDz + kb*8 + tig + 4]);
    }

    float O[8][4];
#pragma unroll
    for (int nt = 0; nt < 8; ++nt)
#pragma unroll
        for (int r = 0; r < 4; ++r) O[nt][r] = 0.f;
    float m0 = -INFINITY, m1 = -INFINITY, l0 = 0.f, l1 = 0.f;

    const int ntiles = 2*qb + 2;

    const int sr = tid >> 2;
    const int sc = (tid & 3) * 16;
    const float* kbase0 = gk + (size_t)bh*Tz*HDz;
    const float* vbase0 = gv + (size_t)bh*Tz*HDz;

    {
        const float* kp = kbase0 + (size_t)sr*HDz + sc;
        const float* vp = vbase0 + (size_t)sr*HDz + sc;
        uint32_t* Kd = Kbuf;
        uint32_t* Vd = Vbuf;
#pragma unroll
        for (int j = 0; j < 4; ++j) {
            float4 k4 = *(const float4*)(kp + j*4);
            uint4 ku = make_uint4(f2tf32(k4.x), f2tf32(k4.y),
                                  f2tf32(k4.z), f2tf32(k4.w));
            *(uint4*)&Kd[sr*KSx + sc + j*4] = ku;
            float4 v4 = *(const float4*)(vp + j*4);
            Vd[(sc + j*4 + 0)*KSx + sr] = f2tf32(v4.x);
            Vd[(sc + j*4 + 1)*KSx + sr] = f2tf32(v4.y);
            Vd[(sc + j*4 + 2)*KSx + sr] = f2tf32(v4.z);
            Vd[(sc + j*4 + 3)*KSx + sr] = f2tf32(v4.w);
        }
    }
    __syncthreads();

    const int srcA = (lane & ~3) | (tig >> 1);
    const int srcB = srcA + 2;

    for (int kt = 0; kt < ntiles; ++kt) {
        const int cur = kt & 1;
        const bool more = (kt + 1 < ntiles);

        float4 kx[4], vx[4];
        if (more) {
            const float* kp = kbase0 + ((size_t)(kt+1)*64 + sr)*HDz + sc;
            const float* vp = vbase0 + ((size_t)(kt+1)*64 + sr)*HDz + sc;
#pragma unroll
            for (int j = 0; j < 4; ++j) {
                kx[j] = *(const float4*)(kp + j*4);
                vx[j] = *(const float4*)(vp + j*4);
            }
        }

        if (kt*64 <= qrow0 + 15) {
            const uint32_t* Ksb = Kbuf + cur*TILE_WORDS;
            const uint32_t* Vsb = Vbuf + cur*TILE_WORDS;

            float sacc[8][4];
#pragma unroll
            for (int nt = 0; nt < 8; ++nt)
#pragma unroll
                for (int r = 0; r < 4; ++r) sacc[nt][r] = 0.f;

#pragma unroll
            for (int kb = 0; kb < 8; ++kb) {
#pragma unroll
                for (int nt = 0; nt < 8; ++nt) {
                    uint32_t b0 = Ksb[(nt*8 + gr)*KSx + kb*8 + tig    ];
                    uint32_t b1 = Ksb[(nt*8 + gr)*KSx + kb*8 + tig + 4];
                    mma_tf32(sacc[nt][0], sacc[nt][1], sacc[nt][2], sacc[nt][3],
                             qf[kb][0], qf[kb][1], qf[kb][2], qf[kb][3],
                             b0, b1);
                }
            }

            const bool bnd = (kt*64 + 63 > qrow0);
            if (bnd) {
                const int r0 = qrow0 + gr, r1 = qrow0 + gr + 8;
#pragma unroll
                for (int nt = 0; nt < 8; ++nt) {
                    const int c0 = kt*64 + nt*8 + 2*tig;
                    sacc[nt][0] = (c0     > r0) ? -1e30f : sacc[nt][0]*scale;
                    sacc[nt][1] = (c0 + 1 > r0) ? -1e30f : sacc[nt][1]*scale;
                    sacc[nt][2] = (c0     > r1) ? -1e30f : sacc[nt][2]*scale;
                    sacc[nt][3] = (c0 + 1 > r1) ? -1e30f : sacc[nt][3]*scale;
                }
            } else {
#pragma unroll
                for (int nt = 0; nt < 8; ++nt)
#pragma unroll
                    for (int r = 0; r < 4; ++r) sacc[nt][r] *= scale;
            }

            float mx0 = -INFINITY, mx1 = -INFINITY;
#pragma unroll
            for (int nt = 0; nt < 8; ++nt) {
                mx0 = fmaxf(mx0, fmaxf(sacc[nt][0], sacc[nt][1]));
                mx1 = fmaxf(mx1, fmaxf(sacc[nt][2], sacc[nt][3]));
            }
            mx0 = fmaxf(mx0, __shfl_xor_sync(0xffffffffu, mx0, 1));
            mx0 = fmaxf(mx0, __shfl_xor_sync(0xffffffffu, mx0, 2));
            mx1 = fmaxf(mx1, __shfl_xor_sync(0xffffffffu, mx1, 1));
            mx1 = fmaxf(mx1, __shfl_xor_sync(0xffffffffu, mx1, 2));

            const float mn0 = fmaxf(m0, mx0);
            const float mn1 = fmaxf(m1, mx1);
            const float a0 = __expf(m0 - mn0);
            const float a1 = __expf(m1 - mn1);
            m0 = mn0; m1 = mn1;

            float s0 = 0.f, s1 = 0.f;
#pragma unroll
            for (int nt = 0; nt < 8; ++nt) {
                sacc[nt][0] = __expf(sacc[nt][0] - mn0);
                sacc[nt][1] = __expf(sacc[nt][1] - mn0);
                sacc[nt][2] = __expf(sacc[nt][2] - mn1);
                sacc[nt][3] = __expf(sacc[nt][3] - mn1);
                s0 += sacc[nt][0] + sacc[nt][1];
                s1 += sacc[nt][2] + sacc[nt][3];
            }
            s0 += __shfl_xor_sync(0xffffffffu, s0, 1);
            s0 += __shfl_xor_sync(0xffffffffu, s0, 2);
            s1 += __shfl_xor_sync(0xffffffffu, s1, 1);
            s1 += __shfl_xor_sync(0xffffffffu, s1, 2);
            l0 = l0*a0 + s0;
            l1 = l1*a1 + s1;

#pragma unroll
            for (int nt = 0; nt < 8; ++nt) {
                O[nt][0] *= a0;  O[nt][1] *= a0;
                O[nt][2] *= a1;  O[nt][3] *= a1;
            }

#pragma unroll
            for (int nt = 0; nt < 8; ++nt)
#pragma unroll
                for (int r = 0; r < 4; ++r)
                    sacc[nt][r] = __uint_as_float(f2tf32(sacc[nt][r]));

#pragma unroll
            for (int kb = 0; kb < 8; ++kb) {
                float e, o;
                e = __shfl_sync(0xffffffffu, sacc[kb][0], srcA);
                o = __shfl_sync(0xffffffffu, sacc[kb][1], srcA);
                const uint32_t pa0 = __float_as_uint((tig & 1) ? o : e);
                e = __shfl_sync(0xffffffffu, sacc[kb][2], srcA);
                o = __shfl_sync(0xffffffffu, sacc[kb][3], srcA);
                const uint32_t pa1 = __float_as_uint((tig & 1) ? o : e);
                e = __shfl_sync(0xffffffffu, sacc[kb][0], srcB);
                o = __shfl_sync(0xffffffffu, sacc[kb][1], srcB);
                const uint32_t pa2 = __float_as_uint((tig & 1) ? o : e);
                e = __shfl_sync(0xffffffffu, sacc[kb][2], srcB);
                o = __shfl_sync(0xffffffffu, sacc[kb][3], srcB);
                const uint32_t pa3 = __float_as_uint((tig & 1) ? o : e);

#pragma unroll
                for (int nt = 0; nt < 8; ++nt) {
                    uint32_t b0 = Vsb[(nt*8 + gr)*KSx + kb*8 + tig    ];
                    uint32_t b1 = Vsb[(nt*8 + gr)*KSx + kb*8 + tig + 4];
                    mma_tf32(O[nt][0], O[nt][1], O[nt][2], O[nt][3],
                             pa0, pa1, pa2, pa3, b0, b1);
                }
            }
        }

        // Produce buf cur^1 (last read in tile kt-1; guarded by prior sync)
        if (more) {
            const int nb = cur ^ 1;
            uint32_t* Kd = Kbuf + nb*TILE_WORDS;
            uint32_t* Vd = Vbuf + nb*TILE_WORDS;
#pragma unroll
            for (int j = 0; j < 4; ++j) {
                uint4 ku = make_uint4(f2tf32(kx[j].x), f2tf32(kx[j].y),
                                      f2tf32(kx[j].z), f2tf32(kx[j].w));
                *(uint4*)&Kd[sr*KSx + sc + j*4] = ku;
                Vd[(sc + j*4 + 0)*KSx + sr] = f2tf32(vx[j].x);
                Vd[(sc + j*4 + 1)*KSx + sr] = f2tf32(vx[j].y);
                Vd[(sc + j*4 + 2)*KSx + sr] = f2tf32(vx[j].z);
                Vd[(sc + j*4 + 3)*KSx + sr] = f2tf32(vx[j].w);
            }
        }
        __syncthreads();   // one barrier per k-tile
    }

    const int b = bh / NHz;
    const int h = bh % NHz;
    const float inv0 = 1.f / l0;
    const float inv1 = 1.f / l1;
    const int q0 = qrow0 + gr;
#pragma unroll
    for (int nt = 0; nt < 8; ++nt) {
        const int col = nt*8 + 2*tig;
        float2 w0 = make_float2(O[nt][0]*inv0, O[nt][1]*inv0);
        float2 w1 = make_float2(O[nt][2]*inv1, O[nt][3]*inv1);
        *(float2*)&gy[((size_t)b*Tz + q0    )*Cz + h*HDz + col] = w0;
        *(float2*)&gy[((size_t)b*Tz + q0 + 8)*Cz + h*HDz + col] = w1;
    }
}

// ---------------------------------------------------------------------------
extern "C" void kernel_launch(void* const* d_in, const int* in_sizes, int n_in,
                              void* d_out, int out_size)
{
    (void)in_sizes; (void)n_in; (void)out_size;
    const float* x      = (const float*)d_in[0];
    const float* w_attn = (const float*)d_in[1];
    const float* b_attn = (const float*)d_in[2];
    const float* w_proj = (const float*)d_in[3];
    const float* b_proj = (const float*)d_in[4];
    float* out = (float*)d_out;

    float *pq, *pk, *pv, *py;
    cudaGetSymbolAddress((void**)&pq, g_q);
    cudaGetSymbolAddress((void**)&pk, g_k);
    cudaGetSymbolAddress((void**)&pv, g_v);
    cudaGetSymbolAddress((void**)&py, g_y);

    const int flash_smem = 4 * TILE_WORDS * (int)sizeof(uint32_t);  // 69,632 B
    cudaFuncSetAttribute(flash2_kernel,
                         cudaFuncAttributeMaxDynamicSharedMemorySize, flash_smem);

    // 1) QKV = x @ w_attn + b_attn (tf32, fragment-major), scatter q/k/v
    {
        dim3 grid(3*Cz/128, Mz/128);
        tgemm_kernel<0><<<grid, 256>>>(x, w_attn, b_attn, nullptr,
                                       Mz, 3*Cz, Cz);
    }
    // 2) Flash attention v2 into g_y
    {
        dim3 grid(Bz*NHz, Tz/128);
        flash2_kernel<<<grid, 256, flash_smem>>>(pq, pk, pv, py);
    }
    // 3) out = g_y @ w_proj + b_proj (tf32, fragment-major)
    {
        dim3 grid(Cz/128, Mz/128);
        tgemm_kernel<1><<<grid, 256>>>(py, w_proj, b_proj, out,
                                       Mz, Cz, Cz);
    }
}

// round 7
// speedup vs baseline: 1.5704x; 1.2451x over previous
#include <cuda_runtime.h>
#include <cuda_fp16.h>
#include <math.h>
#include <stdint.h>

// Problem constants
#define Bz 8
#define Tz 1024
#define Cz 768
#define NHz 12
#define HDz 64
#define Mz (Bz*Tz)        // 8192

// Scratch (device globals; no allocation)
__device__ float g_q[Bz*NHz*Tz*HDz];
__device__ float g_k[Bz*NHz*Tz*HDz];
__device__ float g_v[Bz*NHz*Tz*HDz];
__device__ float g_y[Bz*Tz*Cz];

__device__ __forceinline__ uint32_t pack2(float lo, float hi) {
    __half2 h = __floats2half2_rn(lo, hi);   // .x = lo (low 16 bits)
    return *reinterpret_cast<uint32_t*>(&h);
}

__device__ __forceinline__ void mma_f16(
    float& d0, float& d1, float& d2, float& d3,
    uint32_t a0, uint32_t a1, uint32_t a2, uint32_t a3,
    uint32_t b0, uint32_t b1)
{
    asm volatile(
        "mma.sync.aligned.m16n8k16.row.col.f32.f16.f16.f32 "
        "{%0,%1,%2,%3}, {%4,%5,%6,%7}, {%8,%9}, {%0,%1,%2,%3};\n"
        : "+f"(d0), "+f"(d1), "+f"(d2), "+f"(d3)
        : "r"(a0), "r"(a1), "r"(a2), "r"(a3), "r"(b0), "r"(b1));
}

// ---------------------------------------------------------------------------
// FP16 GEMM: 128x128 CTA tile, K-stage 32 floats (16 half2 words),
// fragment-major smem (word-isomorphic to R6 tf32 layout), 1 sync/stage.
// ---------------------------------------------------------------------------
#define AFW 2112   // 16 tiles * 132 words
#define BFW 2112   // 32 tiles * 66 words

template <int EPI>
__global__ __launch_bounds__(256) void tgemm_kernel(
    const float* __restrict__ A, const float* __restrict__ Bm,
    const float* __restrict__ bias, float* __restrict__ Cout,
    int M, int N, int K)
{
    __shared__ __align__(16) uint32_t Afr[2][AFW];
    __shared__ __align__(16) uint32_t Bfr[2][BFW];

    const int tid  = threadIdx.x;
    const int wid  = tid >> 5;
    const int lane = tid & 31;
    const int wm   = wid & 1;
    const int wn   = wid >> 1;
    const int gr   = lane >> 2;
    const int tig  = lane & 3;
    const int bm   = blockIdx.y * 128;
    const int bn   = blockIdx.x * 128;

    // ---- Producer geometry ----
    // A: rows ar0, ar0+64; kwords kw0..kw0+3 (halves 2kw0..2kw0+7)
    const int ar0 = tid >> 2;            // 0..63
    const int kw0 = (tid & 3) * 4;       // word offset 0,4,8,12
    const int pks = kw0 >> 3;
    const int pkh = (kw0 >> 2) & 1;
    const int agr = ar0 & 7;
    const int ag2 = (agr >> 1) & 3;
    const int awb0 = ((ar0      >> 4)*2 + pks)*132 + agr*16 + pkh*2 + ((ar0 >> 3) & 1);
    const int awb1 = (((ar0+64) >> 4)*2 + pks)*132 + agr*16 + pkh*2 + (((ar0+64) >> 3) & 1);
    // B: kword rows bk, bk+8; n cols bn0..bn0+3
    const int bk   = tid >> 5;           // 0..7
    const int bn0  = (tid & 31) * 4;
    const int btig = bk & 3;
    const int bkh  = (bk >> 2) & 1;
    const int bcom = (bn0 >> 3)*66 + ((bn0 & 7)*4 + btig)*2 + bkh;
    const int bwb0 = bcom;
    const int bwb1 = 16*66 + bcom;

    const float* Ap0 = A + (size_t)(bm + ar0)      * K + (tid & 3) * 8;
    const float* Ap1 = A + (size_t)(bm + ar0 + 64) * K + (tid & 3) * 8;
    // gmem k rows for kword rows bk / bk+8:
    const float* Bp00 = Bm + (size_t)(2*bk    ) * N + bn + bn0;
    const float* Bp01 = Bm + (size_t)(2*bk + 1) * N + bn + bn0;
    const float* Bp10 = Bm + (size_t)(2*bk + 16) * N + bn + bn0;
    const float* Bp11 = Bm + (size_t)(2*bk + 17) * N + bn + bn0;

    const int aswz  = (lane ^ ((lane >> 3) & 3)) * 4;
    const int boff2 = lane * 2;

    float acc[4][4][4];
#pragma unroll
    for (int i = 0; i < 4; ++i)
#pragma unroll
        for (int j = 0; j < 4; ++j)
#pragma unroll
            for (int r = 0; r < 4; ++r) acc[i][j][r] = 0.f;

    const int nstages = K / 32;   // 24

    // ---- Prologue: stage 0 -> buf 0 ----
    {
        float4 a0lo = *(const float4*)(Ap0);
        float4 a0hi = *(const float4*)(Ap0 + 4);
        float4 a1lo = *(const float4*)(Ap1);
        float4 a1hi = *(const float4*)(Ap1 + 4);
        float4 b00 = *(const float4*)(Bp00);
        float4 b01 = *(const float4*)(Bp01);
        float4 b10 = *(const float4*)(Bp10);
        float4 b11 = *(const float4*)(Bp11);
        uint32_t* Au = Afr[0];
        uint32_t* Bu = Bfr[0];
        Au[awb0 + ((0^ag2)<<2)] = pack2(a0lo.x, a0lo.y);
        Au[awb0 + ((1^ag2)<<2)] = pack2(a0lo.z, a0lo.w);
        Au[awb0 + ((2^ag2)<<2)] = pack2(a0hi.x, a0hi.y);
        Au[awb0 + ((3^ag2)<<2)] = pack2(a0hi.z, a0hi.w);
        Au[awb1 + ((0^ag2)<<2)] = pack2(a1lo.x, a1lo.y);
        Au[awb1 + ((1^ag2)<<2)] = pack2(a1lo.z, a1lo.w);
        Au[awb1 + ((2^ag2)<<2)] = pack2(a1hi.x, a1hi.y);
        Au[awb1 + ((3^ag2)<<2)] = pack2(a1hi.z, a1hi.w);
        Bu[bwb0     ] = pack2(b00.x, b01.x);
        Bu[bwb0 +  8] = pack2(b00.y, b01.y);
        Bu[bwb0 + 16] = pack2(b00.z, b01.z);
        Bu[bwb0 + 24] = pack2(b00.w, b01.w);
        Bu[bwb1     ] = pack2(b10.x, b11.x);
        Bu[bwb1 +  8] = pack2(b10.y, b11.y);
        Bu[bwb1 + 16] = pack2(b10.z, b11.z);
        Bu[bwb1 + 24] = pack2(b10.w, b11.w);
    }
    __syncthreads();

    for (int s = 0; s < nstages; ++s) {
        const int buf = s & 1;
        const bool more = (s + 1 < nstages);

        float4 a0lo, a0hi, a1lo, a1hi, b00, b01, b10, b11;
        if (more) {
            const int ko = (s + 1) * 32;
            a0lo = *(const float4*)(Ap0 + ko);
            a0hi = *(const float4*)(Ap0 + ko + 4);
            a1lo = *(const float4*)(Ap1 + ko);
            a1hi = *(const float4*)(Ap1 + ko + 4);
            const size_t bo = (size_t)ko * N;
            b00 = *(const float4*)(Bp00 + bo);
            b01 = *(const float4*)(Bp01 + bo);
            b10 = *(const float4*)(Bp10 + bo);
            b11 = *(const float4*)(Bp11 + bo);
        }

        // ---- Consume buf: 2 k16-steps x 16 mma ----
        const uint32_t* Af = Afr[buf];
        const uint32_t* Bf = Bfr[buf];
#pragma unroll
        for (int ks = 0; ks < 2; ++ks) {
            uint4 af[4];
#pragma unroll
            for (int mt = 0; mt < 4; ++mt)
                af[mt] = *(const uint4*)&Af[((wm*4 + mt)*2 + ks)*132 + aswz];
            uint2 bf[4];
#pragma unroll
            for (int nt = 0; nt < 4; ++nt)
                bf[nt] = *(const uint2*)&Bf[(ks*16 + wn*4 + nt)*66 + boff2];
#pragma unroll
            for (int mt = 0; mt < 4; ++mt)
#pragma unroll
                for (int nt = 0; nt < 4; ++nt)
                    mma_f16(acc[mt][nt][0], acc[mt][nt][1],
                            acc[mt][nt][2], acc[mt][nt][3],
                            af[mt].x, af[mt].y, af[mt].z, af[mt].w,
                            bf[nt].x, bf[nt].y);
        }

        // ---- Produce buf^1 ----
        if (more) {
            uint32_t* Au = Afr[buf ^ 1];
            uint32_t* Bu = Bfr[buf ^ 1];
            Au[awb0 + ((0^ag2)<<2)] = pack2(a0lo.x, a0lo.y);
            Au[awb0 + ((1^ag2)<<2)] = pack2(a0lo.z, a0lo.w);
            Au[awb0 + ((2^ag2)<<2)] = pack2(a0hi.x, a0hi.y);
            Au[awb0 + ((3^ag2)<<2)] = pack2(a0hi.z, a0hi.w);
            Au[awb1 + ((0^ag2)<<2)] = pack2(a1lo.x, a1lo.y);
            Au[awb1 + ((1^ag2)<<2)] = pack2(a1lo.z, a1lo.w);
            Au[awb1 + ((2^ag2)<<2)] = pack2(a1hi.x, a1hi.y);
            Au[awb1 + ((3^ag2)<<2)] = pack2(a1hi.z, a1hi.w);
            Bu[bwb0     ] = pack2(b00.x, b01.x);
            Bu[bwb0 +  8] = pack2(b00.y, b01.y);
            Bu[bwb0 + 16] = pack2(b00.z, b01.z);
            Bu[bwb0 + 24] = pack2(b00.w, b01.w);
            Bu[bwb1     ] = pack2(b10.x, b11.x);
            Bu[bwb1 +  8] = pack2(b10.y, b11.y);
            Bu[bwb1 + 16] = pack2(b10.z, b11.z);
            Bu[bwb1 + 24] = pack2(b10.w, b11.w);
        }
        __syncthreads();
    }

    // ---- Epilogue (f32 acc + bias; unchanged) ----
#pragma unroll
    for (int mt = 0; mt < 4; ++mt) {
#pragma unroll
        for (int nt = 0; nt < 4; ++nt) {
            const int nb2 = bn + wn*32 + nt*8 + 2*tig;
#pragma unroll
            for (int half = 0; half < 2; ++half) {
                const int m = bm + wm*64 + mt*16 + gr + half*8;
                const float v0 = acc[mt][nt][half*2 + 0] + bias[nb2 + 0];
                const float v1 = acc[mt][nt][half*2 + 1] + bias[nb2 + 1];
                if (EPI == 0) {
                    const int which = nb2 / Cz;
                    const int c = nb2 - which * Cz;
                    const int h = c >> 6;
                    const int d = c & 63;
                    const int b = m >> 10;
                    const int t = m & 1023;
                    float* dst = (which == 0) ? g_q : (which == 1) ? g_k : g_v;
                    float2 val = make_float2(v0, v1);
                    *(float2*)&dst[(((size_t)(b*NHz + h) << 10) + t)*HDz + d] = val;
                } else {
                    float2 val = make_float2(v0, v1);
                    *(float2*)&Cout[(size_t)m*N + nb2] = val;
                }
            }
        }
    }
}

// ---------------------------------------------------------------------------
// Flash attention fp16: 128 q/CTA, 8 warps own 16 rows each, f32 softmax in
// registers, zero-shuffle P->A packing (C col pairs == A half2 pairs).
// K smem [key][36 dwords], V smem [kword][72 d]: both B loads conflict-free.
// Double-buffered, 1 sync per k-tile.
// ---------------------------------------------------------------------------
#define KWS 36
#define VWS 72
#define KTW (64*KWS)   // 2304 words
#define VTW (32*VWS)   // 2304 words

__global__ __launch_bounds__(256) void flash2_kernel(
    const float* __restrict__ gq, const float* __restrict__ gk,
    const float* __restrict__ gv, float* __restrict__ gy)
{
    __shared__ __align__(16) uint32_t Kw[2][KTW];
    __shared__ __align__(16) uint32_t Vw[2][VTW];

    const int bh  = blockIdx.x;
    const int qb  = 7 - blockIdx.y;          // heavy CTAs first
    const int tid = threadIdx.x;
    const int wid = tid >> 5, lane = tid & 31;
    const int gr  = lane >> 2;
    const int tig = lane & 3;

    const int qrow0 = qb*128 + wid*16;
    const float scale = 0.125f;

    // ---- Q fragments (half2 words), rows gr / gr+8 ----
    const float* qbase = gq + ((size_t)bh*Tz + qrow0) * HDz;
    uint32_t qf[4][4];
#pragma unroll
    for (int kb = 0; kb < 4; ++kb) {
        float2 f0 = *(const float2*)(qbase + (size_t)gr*HDz     + kb*16 + 2*tig);
        float2 f1 = *(const float2*)(qbase + (size_t)(gr+8)*HDz + kb*16 + 2*tig);
        float2 f2 = *(const float2*)(qbase + (size_t)gr*HDz     + kb*16 + 2*tig + 8);
        float2 f3 = *(const float2*)(qbase + (size_t)(gr+8)*HDz + kb*16 + 2*tig + 8);
        qf[kb][0] = pack2(f0.x, f0.y);
        qf[kb][1] = pack2(f1.x, f1.y);
        qf[kb][2] = pack2(f2.x, f2.y);
        qf[kb][3] = pack2(f3.x, f3.y);
    }

    float O[8][4];
#pragma unroll
    for (int nt = 0; nt < 8; ++nt)
#pragma unroll
        for (int r = 0; r < 4; ++r) O[nt][r] = 0.f;
    float m0 = -INFINITY, m1 = -INFINITY, l0 = 0.f, l1 = 0.f;

    const int ntiles = 2*qb + 2;

    // staging geometry
    const int sr = tid >> 2;            // K: key row 0..63
    const int sdw = (tid & 3) * 8;      // K: dword offset (floats sdw*2)
    const int vp = tid >> 3;            // V: key-pair 0..31
    const int vdc = (tid & 7) * 8;      // V: d cols vdc..vdc+7
    const float* kbase0 = gk + (size_t)bh*Tz*HDz;
    const float* vbase0 = gv + (size_t)bh*Tz*HDz;

    // ---- Prologue: tile 0 -> buf 0 ----
    {
        const float* kp = kbase0 + (size_t)sr*HDz + sdw*2;
        float4 k0 = *(const float4*)(kp);
        float4 k1 = *(const float4*)(kp + 4);
        float4 k2 = *(const float4*)(kp + 8);
        float4 k3 = *(const float4*)(kp + 12);
        uint4 kwA = make_uint4(pack2(k0.x,k0.y), pack2(k0.z,k0.w),
                               pack2(k1.x,k1.y), pack2(k1.z,k1.w));
        uint4 kwB = make_uint4(pack2(k2.x,k2.y), pack2(k2.z,k2.w),
                               pack2(k3.x,k3.y), pack2(k3.z,k3.w));
        *(uint4*)&Kw[0][sr*KWS + sdw    ] = kwA;
        *(uint4*)&Kw[0][sr*KWS + sdw + 4] = kwB;

        const float* vpl = vbase0 + (size_t)(2*vp)*HDz + vdc;
        float4 v0a = *(const float4*)(vpl);
        float4 v0b = *(const float4*)(vpl + 4);
        float4 v1a = *(const float4*)(vpl + HDz);
        float4 v1b = *(const float4*)(vpl + HDz + 4);
        uint4 vwA = make_uint4(pack2(v0a.x,v1a.x), pack2(v0a.y,v1a.y),
                               pack2(v0a.z,v1a.z), pack2(v0a.w,v1a.w));
        uint4 vwB = make_uint4(pack2(v0b.x,v1b.x), pack2(v0b.y,v1b.y),
                               pack2(v0b.z,v1b.z), pack2(v0b.w,v1b.w));
        *(uint4*)&Vw[0][vp*VWS + vdc    ] = vwA;
        *(uint4*)&Vw[0][vp*VWS + vdc + 4] = vwB;
    }
    __syncthreads();

    for (int kt = 0; kt < ntiles; ++kt) {
        const int cur = kt & 1;
        const bool more = (kt + 1 < ntiles);

        // Prefetch next tile to registers
        float4 k0, k1, k2, k3, v0a, v0b, v1a, v1b;
        if (more) {
            const float* kp = kbase0 + ((size_t)(kt+1)*64 + sr)*HDz + sdw*2;
            k0 = *(const float4*)(kp);
            k1 = *(const float4*)(kp + 4);
            k2 = *(const float4*)(kp + 8);
            k3 = *(const float4*)(kp + 12);
            const float* vpl = vbase0 + ((size_t)(kt+1)*64 + 2*vp)*HDz + vdc;
            v0a = *(const float4*)(vpl);
            v0b = *(const float4*)(vpl + 4);
            v1a = *(const float4*)(vpl + HDz);
            v1b = *(const float4*)(vpl + HDz + 4);
        }

        if (kt*64 <= qrow0 + 15) {
            const uint32_t* Ksb = Kw[cur];
            const uint32_t* Vsb = Vw[cur];

            // ---- S = Q K^T : 4 k16-steps x 8 mma ----
            float sacc[8][4];
#pragma unroll
            for (int nt = 0; nt < 8; ++nt)
#pragma unroll
                for (int r = 0; r < 4; ++r) sacc[nt][r] = 0.f;

#pragma unroll
            for (int kb = 0; kb < 4; ++kb) {
#pragma unroll
                for (int nt = 0; nt < 8; ++nt) {
                    uint32_t b0 = Ksb[(nt*8 + gr)*KWS + kb*8 + tig    ];
                    uint32_t b1 = Ksb[(nt*8 + gr)*KWS + kb*8 + tig + 4];
                    mma_f16(sacc[nt][0], sacc[nt][1], sacc[nt][2], sacc[nt][3],
                            qf[kb][0], qf[kb][1], qf[kb][2], qf[kb][3],
                            b0, b1);
                }
            }

            // ---- scale + causal mask ----
            const bool bnd = (kt*64 + 63 > qrow0);
            if (bnd) {
                const int r0 = qrow0 + gr, r1 = qrow0 + gr + 8;
#pragma unroll
                for (int nt = 0; nt < 8; ++nt) {
                    const int c0 = kt*64 + nt*8 + 2*tig;
                    sacc[nt][0] = (c0     > r0) ? -1e30f : sacc[nt][0]*scale;
                    sacc[nt][1] = (c0 + 1 > r0) ? -1e30f : sacc[nt][1]*scale;
                    sacc[nt][2] = (c0     > r1) ? -1e30f : sacc[nt][2]*scale;
                    sacc[nt][3] = (c0 + 1 > r1) ? -1e30f : sacc[nt][3]*scale;
                }
            } else {
#pragma unroll
                for (int nt = 0; nt < 8; ++nt)
#pragma unroll
                    for (int r = 0; r < 4; ++r) sacc[nt][r] *= scale;
            }

            // ---- register softmax (f32, quad reduce) ----
            float mx0 = -INFINITY, mx1 = -INFINITY;
#pragma unroll
            for (int nt = 0; nt < 8; ++nt) {
                mx0 = fmaxf(mx0, fmaxf(sacc[nt][0], sacc[nt][1]));
                mx1 = fmaxf(mx1, fmaxf(sacc[nt][2], sacc[nt][3]));
            }
            mx0 = fmaxf(mx0, __shfl_xor_sync(0xffffffffu, mx0, 1));
            mx0 = fmaxf(mx0, __shfl_xor_sync(0xffffffffu, mx0, 2));
            mx1 = fmaxf(mx1, __shfl_xor_sync(0xffffffffu, mx1, 1));
            mx1 = fmaxf(mx1, __shfl_xor_sync(0xffffffffu, mx1, 2));

            const float mn0 = fmaxf(m0, mx0);
            const float mn1 = fmaxf(m1, mx1);
            const float a0 = __expf(m0 - mn0);
            const float a1 = __expf(m1 - mn1);
            m0 = mn0; m1 = mn1;

            float s0 = 0.f, s1 = 0.f;
#pragma unroll
            for (int nt = 0; nt < 8; ++nt) {
                sacc[nt][0] = __expf(sacc[nt][0] - mn0);
                sacc[nt][1] = __expf(sacc[nt][1] - mn0);
                sacc[nt][2] = __expf(sacc[nt][2] - mn1);
                sacc[nt][3] = __expf(sacc[nt][3] - mn1);
                s0 += sacc[nt][0] + sacc[nt][1];
                s1 += sacc[nt][2] + sacc[nt][3];
            }
            s0 += __shfl_xor_sync(0xffffffffu, s0, 1);
            s0 += __shfl_xor_sync(0xffffffffu, s0, 2);
            s1 += __shfl_xor_sync(0xffffffffu, s1, 1);
            s1 += __shfl_xor_sync(0xffffffffu, s1, 2);
            l0 = l0*a0 + s0;
            l1 = l1*a1 + s1;

#pragma unroll
            for (int nt = 0; nt < 8; ++nt) {
                O[nt][0] *= a0;  O[nt][1] *= a0;
                O[nt][2] *= a1;  O[nt][3] *= a1;
            }

            // ---- O += P V : zero-shuffle A packing ----
#pragma unroll
            for (int kb = 0; kb < 4; ++kb) {
                const uint32_t pa0 = pack2(sacc[2*kb  ][0], sacc[2*kb  ][1]);
                const uint32_t pa1 = pack2(sacc[2*kb  ][2], sacc[2*kb  ][3]);
                const uint32_t pa2 = pack2(sacc[2*kb+1][0], sacc[2*kb+1][1]);
                const uint32_t pa3 = pack2(sacc[2*kb+1][2], sacc[2*kb+1][3]);
#pragma unroll
                for (int nt = 0; nt < 8; ++nt) {
                    uint32_t b0 = Vsb[(kb*8 + tig    )*VWS + nt*8 + gr];
                    uint32_t b1 = Vsb[(kb*8 + tig + 4)*VWS + nt*8 + gr];
                    mma_f16(O[nt][0], O[nt][1], O[nt][2], O[nt][3],
                            pa0, pa1, pa2, pa3, b0, b1);
                }
            }
        }

        // ---- Produce buf cur^1 ----
        if (more) {
            const int nb = cur ^ 1;
            uint4 kwA = make_uint4(pack2(k0.x,k0.y), pack2(k0.z,k0.w),
                                   pack2(k1.x,k1.y), pack2(k1.z,k1.w));
            uint4 kwB = make_uint4(pack2(k2.x,k2.y), pack2(k2.z,k2.w),
                                   pack2(k3.x,k3.y), pack2(k3.z,k3.w));
            *(uint4*)&Kw[nb][sr*KWS + sdw    ] = kwA;
            *(uint4*)&Kw[nb][sr*KWS + sdw + 4] = kwB;
            uint4 vwA = make_uint4(pack2(v0a.x,v1a.x), pack2(v0a.y,v1a.y),
                                   pack2(v0a.z,v1a.z), pack2(v0a.w,v1a.w));
            uint4 vwB = make_uint4(pack2(v0b.x,v1b.x), pack2(v0b.y,v1b.y),
                                   pack2(v0b.z,v1b.z), pack2(v0b.w,v1b.w));
            *(uint4*)&Vw[nb][vp*VWS + vdc    ] = vwA;
            *(uint4*)&Vw[nb][vp*VWS + vdc + 4] = vwB;
        }
        __syncthreads();
    }

    // ---- Epilogue ----
    const int b = bh / NHz;
    const int h = bh % NHz;
    const float inv0 = 1.f / l0;
    const float inv1 = 1.f / l1;
    const int q0 = qrow0 + gr;
#pragma unroll
    for (int nt = 0; nt < 8; ++nt) {
        const int col = nt*8 + 2*tig;
        float2 w0 = make_float2(O[nt][0]*inv0, O[nt][1]*inv0);
        float2 w1 = make_float2(O[nt][2]*inv1, O[nt][3]*inv1);
        *(float2*)&gy[((size_t)b*Tz + q0    )*Cz + h*HDz + col] = w0;
        *(float2*)&gy[((size_t)b*Tz + q0 + 8)*Cz + h*HDz + col] = w1;
    }
}

// ---------------------------------------------------------------------------
extern "C" void kernel_launch(void* const* d_in, const int* in_sizes, int n_in,
                              void* d_out, int out_size)
{
    (void)in_sizes; (void)n_in; (void)out_size;
    const float* x      = (const float*)d_in[0];
    const float* w_attn = (const float*)d_in[1];
    const float* b_attn = (const float*)d_in[2];
    const float* w_proj = (const float*)d_in[3];
    const float* b_proj = (const float*)d_in[4];
    float* out = (float*)d_out;

    float *pq, *pk, *pv, *py;
    cudaGetSymbolAddress((void**)&pq, g_q);
    cudaGetSymbolAddress((void**)&pk, g_k);
    cudaGetSymbolAddress((void**)&pv, g_v);
    cudaGetSymbolAddress((void**)&py, g_y);

    // 1) QKV = x @ w_attn + b_attn (fp16 mma), scatter q/k/v
    {
        dim3 grid(3*Cz/128, Mz/128);
        tgemm_kernel<0><<<grid, 256>>>(x, w_attn, b_attn, nullptr,
                                       Mz, 3*Cz, Cz);
    }
    // 2) Flash attention fp16 into g_y
    {
        dim3 grid(Bz*NHz, Tz/128);
        flash2_kernel<<<grid, 256>>>(pq, pk, pv, py);
    }
    // 3) out = g_y @ w_proj + b_proj (fp16 mma)
    {
        dim3 grid(Cz/128, Mz/128);
        tgemm_kernel<1><<<grid, 256>>>(py, w_proj, b_proj, out,
                                       Mz, Cz, Cz);
    }
}

// round 8
// speedup vs baseline: 1.9816x; 1.2618x over previous
#include <cuda_runtime.h>
#include <cuda_fp16.h>
#include <math.h>
#include <stdint.h>

// Problem constants
#define Bz 8
#define Tz 1024
#define Cz 768
#define NHz 12
#define HDz 64
#define Mz (Bz*Tz)        // 8192

// Scratch (device globals; no allocation)
__device__ float g_q[Bz*NHz*Tz*HDz];
__device__ float g_k[Bz*NHz*Tz*HDz];
__device__ float g_v[Bz*NHz*Tz*HDz];
__device__ float g_y[Bz*Tz*Cz];

__device__ __forceinline__ uint32_t pack2(float lo, float hi) {
    __half2 h = __floats2half2_rn(lo, hi);   // .x = lo (low 16 bits)
    return *reinterpret_cast<uint32_t*>(&h);
}

__device__ __forceinline__ void mma_f16(
    float& d0, float& d1, float& d2, float& d3,
    uint32_t a0, uint32_t a1, uint32_t a2, uint32_t a3,
    uint32_t b0, uint32_t b1)
{
    asm volatile(
        "mma.sync.aligned.m16n8k16.row.col.f32.f16.f16.f32 "
        "{%0,%1,%2,%3}, {%4,%5,%6,%7}, {%8,%9}, {%0,%1,%2,%3};\n"
        : "+f"(d0), "+f"(d1), "+f"(d2), "+f"(d3)
        : "r"(a0), "r"(a1), "r"(a2), "r"(a3), "r"(b0), "r"(b1));
}

// ---------------------------------------------------------------------------
// FP16 GEMM: 128x128 CTA tile, K-stage 32 floats (16 half2 words),
// fragment-major smem, 1 sync/stage. __launch_bounds__(256,2) pins regs<=128
// so 2 CTAs/SM co-reside (R7 ran at 162 regs -> 1 CTA/SM -> issue starvation).
// ---------------------------------------------------------------------------
#define AFW 2112   // 16 tiles * 132 words
#define BFW 2112   // 32 tiles * 66 words

template <int EPI>
__global__ __launch_bounds__(256, 2) void tgemm_kernel(
    const float* __restrict__ A, const float* __restrict__ Bm,
    const float* __restrict__ bias, float* __restrict__ Cout,
    int M, int N, int K)
{
    __shared__ __align__(16) uint32_t Afr[2][AFW];
    __shared__ __align__(16) uint32_t Bfr[2][BFW];

    const int tid  = threadIdx.x;
    const int wid  = tid >> 5;
    const int lane = tid & 31;
    const int wm   = wid & 1;
    const int wn   = wid >> 1;
    const int gr   = lane >> 2;
    const int tig  = lane & 3;
    const int bm   = blockIdx.y * 128;
    const int bn   = blockIdx.x * 128;

    // ---- Producer geometry ----
    const int ar0 = tid >> 2;            // 0..63
    const int kw0 = (tid & 3) * 4;       // word offset 0,4,8,12
    const int pks = kw0 >> 3;
    const int pkh = (kw0 >> 2) & 1;
    const int agr = ar0 & 7;
    const int ag2 = (agr >> 1) & 3;
    const int awb0 = ((ar0      >> 4)*2 + pks)*132 + agr*16 + pkh*2 + ((ar0 >> 3) & 1);
    const int awb1 = (((ar0+64) >> 4)*2 + pks)*132 + agr*16 + pkh*2 + (((ar0+64) >> 3) & 1);
    const int bk   = tid >> 5;           // 0..7
    const int bn0  = (tid & 31) * 4;
    const int btig = bk & 3;
    const int bkh  = (bk >> 2) & 1;
    const int bcom = (bn0 >> 3)*66 + ((bn0 & 7)*4 + btig)*2 + bkh;
    const int bwb0 = bcom;
    const int bwb1 = 16*66 + bcom;

    const float* Ap0 = A + (size_t)(bm + ar0)      * K + (tid & 3) * 8;
    const float* Ap1 = A + (size_t)(bm + ar0 + 64) * K + (tid & 3) * 8;
    const float* Bp00 = Bm + (size_t)(2*bk    ) * N + bn + bn0;
    const float* Bp01 = Bm + (size_t)(2*bk + 1) * N + bn + bn0;
    const float* Bp10 = Bm + (size_t)(2*bk + 16) * N + bn + bn0;
    const float* Bp11 = Bm + (size_t)(2*bk + 17) * N + bn + bn0;

    const int aswz  = (lane ^ ((lane >> 3) & 3)) * 4;
    const int boff2 = lane * 2;

    float acc[4][4][4];
#pragma unroll
    for (int i = 0; i < 4; ++i)
#pragma unroll
        for (int j = 0; j < 4; ++j)
#pragma unroll
            for (int r = 0; r < 4; ++r) acc[i][j][r] = 0.f;

    const int nstages = K / 32;   // 24

    // ---- Prologue: stage 0 -> buf 0 ----
    {
        float4 a0lo = *(const float4*)(Ap0);
        float4 a0hi = *(const float4*)(Ap0 + 4);
        float4 a1lo = *(const float4*)(Ap1);
        float4 a1hi = *(const float4*)(Ap1 + 4);
        float4 b00 = *(const float4*)(Bp00);
        float4 b01 = *(const float4*)(Bp01);
        float4 b10 = *(const float4*)(Bp10);
        float4 b11 = *(const float4*)(Bp11);
        uint32_t* Au = Afr[0];
        uint32_t* Bu = Bfr[0];
        Au[awb0 + ((0^ag2)<<2)] = pack2(a0lo.x, a0lo.y);
        Au[awb0 + ((1^ag2)<<2)] = pack2(a0lo.z, a0lo.w);
        Au[awb0 + ((2^ag2)<<2)] = pack2(a0hi.x, a0hi.y);
        Au[awb0 + ((3^ag2)<<2)] = pack2(a0hi.z, a0hi.w);
        Au[awb1 + ((0^ag2)<<2)] = pack2(a1lo.x, a1lo.y);
        Au[awb1 + ((1^ag2)<<2)] = pack2(a1lo.z, a1lo.w);
        Au[awb1 + ((2^ag2)<<2)] = pack2(a1hi.x, a1hi.y);
        Au[awb1 + ((3^ag2)<<2)] = pack2(a1hi.z, a1hi.w);
        Bu[bwb0     ] = pack2(b00.x, b01.x);
        Bu[bwb0 +  8] = pack2(b00.y, b01.y);
        Bu[bwb0 + 16] = pack2(b00.z, b01.z);
        Bu[bwb0 + 24] = pack2(b00.w, b01.w);
        Bu[bwb1     ] = pack2(b10.x, b11.x);
        Bu[bwb1 +  8] = pack2(b10.y, b11.y);
        Bu[bwb1 + 16] = pack2(b10.z, b11.z);
        Bu[bwb1 + 24] = pack2(b10.w, b11.w);
    }
    __syncthreads();

    for (int s = 0; s < nstages; ++s) {
        const int buf = s & 1;
        const bool more = (s + 1 < nstages);

        float4 a0lo, a0hi, a1lo, a1hi, b00, b01, b10, b11;
        if (more) {
            const int ko = (s + 1) * 32;
            a0lo = *(const float4*)(Ap0 + ko);
            a0hi = *(const float4*)(Ap0 + ko + 4);
            a1lo = *(const float4*)(Ap1 + ko);
            a1hi = *(const float4*)(Ap1 + ko + 4);
            const size_t bo = (size_t)ko * N;
            b00 = *(const float4*)(Bp00 + bo);
            b01 = *(const float4*)(Bp01 + bo);
            b10 = *(const float4*)(Bp10 + bo);
            b11 = *(const float4*)(Bp11 + bo);
        }

        // ---- Consume buf: 2 k16-steps x 16 mma ----
        const uint32_t* Af = Afr[buf];
        const uint32_t* Bf = Bfr[buf];
#pragma unroll
        for (int ks = 0; ks < 2; ++ks) {
            uint4 af[4];
#pragma unroll
            for (int mt = 0; mt < 4; ++mt)
                af[mt] = *(const uint4*)&Af[((wm*4 + mt)*2 + ks)*132 + aswz];
            uint2 bf[4];
#pragma unroll
            for (int nt = 0; nt < 4; ++nt)
                bf[nt] = *(const uint2*)&Bf[(ks*16 + wn*4 + nt)*66 + boff2];
#pragma unroll
            for (int mt = 0; mt < 4; ++mt)
#pragma unroll
                for (int nt = 0; nt < 4; ++nt)
                    mma_f16(acc[mt][nt][0], acc[mt][nt][1],
                            acc[mt][nt][2], acc[mt][nt][3],
                            af[mt].x, af[mt].y, af[mt].z, af[mt].w,
                            bf[nt].x, bf[nt].y);
        }

        // ---- Produce buf^1 ----
        if (more) {
            uint32_t* Au = Afr[buf ^ 1];
            uint32_t* Bu = Bfr[buf ^ 1];
            Au[awb0 + ((0^ag2)<<2)] = pack2(a0lo.x, a0lo.y);
            Au[awb0 + ((1^ag2)<<2)] = pack2(a0lo.z, a0lo.w);
            Au[awb0 + ((2^ag2)<<2)] = pack2(a0hi.x, a0hi.y);
            Au[awb0 + ((3^ag2)<<2)] = pack2(a0hi.z, a0hi.w);
            Au[awb1 + ((0^ag2)<<2)] = pack2(a1lo.x, a1lo.y);
            Au[awb1 + ((1^ag2)<<2)] = pack2(a1lo.z, a1lo.w);
            Au[awb1 + ((2^ag2)<<2)] = pack2(a1hi.x, a1hi.y);
            Au[awb1 + ((3^ag2)<<2)] = pack2(a1hi.z, a1hi.w);
            Bu[bwb0     ] = pack2(b00.x, b01.x);
            Bu[bwb0 +  8] = pack2(b00.y, b01.y);
            Bu[bwb0 + 16] = pack2(b00.z, b01.z);
            Bu[bwb0 + 24] = pack2(b00.w, b01.w);
            Bu[bwb1     ] = pack2(b10.x, b11.x);
            Bu[bwb1 +  8] = pack2(b10.y, b11.y);
            Bu[bwb1 + 16] = pack2(b10.z, b11.z);
            Bu[bwb1 + 24] = pack2(b10.w, b11.w);
        }
        __syncthreads();
    }

    // ---- Epilogue (f32 acc + bias; unchanged) ----
#pragma unroll
    for (int mt = 0; mt < 4; ++mt) {
#pragma unroll
        for (int nt = 0; nt < 4; ++nt) {
            const int nb2 = bn + wn*32 + nt*8 + 2*tig;
#pragma unroll
            for (int half = 0; half < 2; ++half) {
                const int m = bm + wm*64 + mt*16 + gr + half*8;
                const float v0 = acc[mt][nt][half*2 + 0] + bias[nb2 + 0];
                const float v1 = acc[mt][nt][half*2 + 1] + bias[nb2 + 1];
                if (EPI == 0) {
                    const int which = nb2 / Cz;
                    const int c = nb2 - which * Cz;
                    const int h = c >> 6;
                    const int d = c & 63;
                    const int b = m >> 10;
                    const int t = m & 1023;
                    float* dst = (which == 0) ? g_q : (which == 1) ? g_k : g_v;
                    float2 val = make_float2(v0, v1);
                    *(float2*)&dst[(((size_t)(b*NHz + h) << 10) + t)*HDz + d] = val;
                } else {
                    float2 val = make_float2(v0, v1);
                    *(float2*)&Cout[(size_t)m*N + nb2] = val;
                }
            }
        }
    }
}

// ---------------------------------------------------------------------------
// Flash attention fp16 (unchanged from R7).
// ---------------------------------------------------------------------------
#define KWS 36
#define VWS 72
#define KTW (64*KWS)
#define VTW (32*VWS)

__global__ __launch_bounds__(256) void flash2_kernel(
    const float* __restrict__ gq, const float* __restrict__ gk,
    const float* __restrict__ gv, float* __restrict__ gy)
{
    __shared__ __align__(16) uint32_t Kw[2][KTW];
    __shared__ __align__(16) uint32_t Vw[2][VTW];

    const int bh  = blockIdx.x;
    const int qb  = 7 - blockIdx.y;
    const int tid = threadIdx.x;
    const int wid = tid >> 5, lane = tid & 31;
    const int gr  = lane >> 2;
    const int tig = lane & 3;

    const int qrow0 = qb*128 + wid*16;
    const float scale = 0.125f;

    const float* qbase = gq + ((size_t)bh*Tz + qrow0) * HDz;
    uint32_t qf[4][4];
#pragma unroll
    for (int kb = 0; kb < 4; ++kb) {
        float2 f0 = *(const float2*)(qbase + (size_t)gr*HDz     + kb*16 + 2*tig);
        float2 f1 = *(const float2*)(qbase + (size_t)(gr+8)*HDz + kb*16 + 2*tig);
        float2 f2 = *(const float2*)(qbase + (size_t)gr*HDz     + kb*16 + 2*tig + 8);
        float2 f3 = *(const float2*)(qbase + (size_t)(gr+8)*HDz + kb*16 + 2*tig + 8);
        qf[kb][0] = pack2(f0.x, f0.y);
        qf[kb][1] = pack2(f1.x, f1.y);
        qf[kb][2] = pack2(f2.x, f2.y);
        qf[kb][3] = pack2(f3.x, f3.y);
    }

    float O[8][4];
#pragma unroll
    for (int nt = 0; nt < 8; ++nt)
#pragma unroll
        for (int r = 0; r < 4; ++r) O[nt][r] = 0.f;
    float m0 = -INFINITY, m1 = -INFINITY, l0 = 0.f, l1 = 0.f;

    const int ntiles = 2*qb + 2;

    const int sr = tid >> 2;
    const int sdw = (tid & 3) * 8;
    const int vp = tid >> 3;
    const int vdc = (tid & 7) * 8;
    const float* kbase0 = gk + (size_t)bh*Tz*HDz;
    const float* vbase0 = gv + (size_t)bh*Tz*HDz;

    {
        const float* kp = kbase0 + (size_t)sr*HDz + sdw*2;
        float4 k0 = *(const float4*)(kp);
        float4 k1 = *(const float4*)(kp + 4);
        float4 k2 = *(const float4*)(kp + 8);
        float4 k3 = *(const float4*)(kp + 12);
        uint4 kwA = make_uint4(pack2(k0.x,k0.y), pack2(k0.z,k0.w),
                               pack2(k1.x,k1.y), pack2(k1.z,k1.w));
        uint4 kwB = make_uint4(pack2(k2.x,k2.y), pack2(k2.z,k2.w),
                               pack2(k3.x,k3.y), pack2(k3.z,k3.w));
        *(uint4*)&Kw[0][sr*KWS + sdw    ] = kwA;
        *(uint4*)&Kw[0][sr*KWS + sdw + 4] = kwB;

        const float* vpl = vbase0 + (size_t)(2*vp)*HDz + vdc;
        float4 v0a = *(const float4*)(vpl);
        float4 v0b = *(const float4*)(vpl + 4);
        float4 v1a = *(const float4*)(vpl + HDz);
        float4 v1b = *(const float4*)(vpl + HDz + 4);
        uint4 vwA = make_uint4(pack2(v0a.x,v1a.x), pack2(v0a.y,v1a.y),
                               pack2(v0a.z,v1a.z), pack2(v0a.w,v1a.w));
        uint4 vwB = make_uint4(pack2(v0b.x,v1b.x), pack2(v0b.y,v1b.y),
                               pack2(v0b.z,v1b.z), pack2(v0b.w,v1b.w));
        *(uint4*)&Vw[0][vp*VWS + vdc    ] = vwA;
        *(uint4*)&Vw[0][vp*VWS + vdc + 4] = vwB;
    }
    __syncthreads();

    for (int kt = 0; kt < ntiles; ++kt) {
        const int cur = kt & 1;
        const bool more = (kt + 1 < ntiles);

        float4 k0, k1, k2, k3, v0a, v0b, v1a, v1b;
        if (more) {
            const float* kp = kbase0 + ((size_t)(kt+1)*64 + sr)*HDz + sdw*2;
            k0 = *(const float4*)(kp);
            k1 = *(const float4*)(kp + 4);
            k2 = *(const float4*)(kp + 8);
            k3 = *(const float4*)(kp + 12);
            const float* vpl = vbase0 + ((size_t)(kt+1)*64 + 2*vp)*HDz + vdc;
            v0a = *(const float4*)(vpl);
            v0b = *(const float4*)(vpl + 4);
            v1a = *(const float4*)(vpl + HDz);
            v1b = *(const float4*)(vpl + HDz + 4);
        }

        if (kt*64 <= qrow0 + 15) {
            const uint32_t* Ksb = Kw[cur];
            const uint32_t* Vsb = Vw[cur];

            float sacc[8][4];
#pragma unroll
            for (int nt = 0; nt < 8; ++nt)
#pragma unroll
                for (int r = 0; r < 4; ++r) sacc[nt][r] = 0.f;

#pragma unroll
            for (int kb = 0; kb < 4; ++kb) {
#pragma unroll
                for (int nt = 0; nt < 8; ++nt) {
                    uint32_t b0 = Ksb[(nt*8 + gr)*KWS + kb*8 + tig    ];
                    uint32_t b1 = Ksb[(nt*8 + gr)*KWS + kb*8 + tig + 4];
                    mma_f16(sacc[nt][0], sacc[nt][1], sacc[nt][2], sacc[nt][3],
                            qf[kb][0], qf[kb][1], qf[kb][2], qf[kb][3],
                            b0, b1);
                }
            }

            const bool bnd = (kt*64 + 63 > qrow0);
            if (bnd) {
                const int r0 = qrow0 + gr, r1 = qrow0 + gr + 8;
#pragma unroll
                for (int nt = 0; nt < 8; ++nt) {
                    const int c0 = kt*64 + nt*8 + 2*tig;
                    sacc[nt][0] = (c0     > r0) ? -1e30f : sacc[nt][0]*scale;
                    sacc[nt][1] = (c0 + 1 > r0) ? -1e30f : sacc[nt][1]*scale;
                    sacc[nt][2] = (c0     > r1) ? -1e30f : sacc[nt][2]*scale;
                    sacc[nt][3] = (c0 + 1 > r1) ? -1e30f : sacc[nt][3]*scale;
                }
            } else {
#pragma unroll
                for (int nt = 0; nt < 8; ++nt)
#pragma unroll
                    for (int r = 0; r < 4; ++r) sacc[nt][r] *= scale;
            }

            float mx0 = -INFINITY, mx1 = -INFINITY;
#pragma unroll
            for (int nt = 0; nt < 8; ++nt) {
                mx0 = fmaxf(mx0, fmaxf(sacc[nt][0], sacc[nt][1]));
                mx1 = fmaxf(mx1, fmaxf(sacc[nt][2], sacc[nt][3]));
            }
            mx0 = fmaxf(mx0, __shfl_xor_sync(0xffffffffu, mx0, 1));
            mx0 = fmaxf(mx0, __shfl_xor_sync(0xffffffffu, mx0, 2));
            mx1 = fmaxf(mx1, __shfl_xor_sync(0xffffffffu, mx1, 1));
            mx1 = fmaxf(mx1, __shfl_xor_sync(0xffffffffu, mx1, 2));

            const float mn0 = fmaxf(m0, mx0);
            const float mn1 = fmaxf(m1, mx1);
            const float a0 = __expf(m0 - mn0);
            const float a1 = __expf(m1 - mn1);
            m0 = mn0; m1 = mn1;

            float s0 = 0.f, s1 = 0.f;
#pragma unroll
            for (int nt = 0; nt < 8; ++nt) {
                sacc[nt][0] = __expf(sacc[nt][0] - mn0);
                sacc[nt][1] = __expf(sacc[nt][1] - mn0);
                sacc[nt][2] = __expf(sacc[nt][2] - mn1);
                sacc[nt][3] = __expf(sacc[nt][3] - mn1);
                s0 += sacc[nt][0] + sacc[nt][1];
                s1 += sacc[nt][2] + sacc[nt][3];
            }
            s0 += __shfl_xor_sync(0xffffffffu, s0, 1);
            s0 += __shfl_xor_sync(0xffffffffu, s0, 2);
            s1 += __shfl_xor_sync(0xffffffffu, s1, 1);
            s1 += __shfl_xor_sync(0xffffffffu, s1, 2);
            l0 = l0*a0 + s0;
            l1 = l1*a1 + s1;

#pragma unroll
            for (int nt = 0; nt < 8; ++nt) {
                O[nt][0] *= a0;  O[nt][1] *= a0;
                O[nt][2] *= a1;  O[nt][3] *= a1;
            }

#pragma unroll
            for (int kb = 0; kb < 4; ++kb) {
                const uint32_t pa0 = pack2(sacc[2*kb  ][0], sacc[2*kb  ][1]);
                const uint32_t pa1 = pack2(sacc[2*kb  ][2], sacc[2*kb  ][3]);
                const uint32_t pa2 = pack2(sacc[2*kb+1][0], sacc[2*kb+1][1]);
                const uint32_t pa3 = pack2(sacc[2*kb+1][2], sacc[2*kb+1][3]);
#pragma unroll
                for (int nt = 0; nt < 8; ++nt) {
                    uint32_t b0 = Vsb[(kb*8 + tig    )*VWS + nt*8 + gr];
                    uint32_t b1 = Vsb[(kb*8 + tig + 4)*VWS + nt*8 + gr];
                    mma_f16(O[nt][0], O[nt][1], O[nt][2], O[nt][3],
                            pa0, pa1, pa2, pa3, b0, b1);
                }
            }
        }

        if (more) {
            const int nb = cur ^ 1;
            uint4 kwA = make_uint4(pack2(k0.x,k0.y), pack2(k0.z,k0.w),
                                   pack2(k1.x,k1.y), pack2(k1.z,k1.w));
            uint4 kwB = make_uint4(pack2(k2.x,k2.y), pack2(k2.z,k2.w),
                                   pack2(k3.x,k3.y), pack2(k3.z,k3.w));
            *(uint4*)&Kw[nb][sr*KWS + sdw    ] = kwA;
            *(uint4*)&Kw[nb][sr*KWS + sdw + 4] = kwB;
            uint4 vwA = make_uint4(pack2(v0a.x,v1a.x), pack2(v0a.y,v1a.y),
                                   pack2(v0a.z,v1a.z), pack2(v0a.w,v1a.w));
            uint4 vwB = make_uint4(pack2(v0b.x,v1b.x), pack2(v0b.y,v1b.y),
                                   pack2(v0b.z,v1b.z), pack2(v0b.w,v1b.w));
            *(uint4*)&Vw[nb][vp*VWS + vdc    ] = vwA;
            *(uint4*)&Vw[nb][vp*VWS + vdc + 4] = vwB;
        }
        __syncthreads();
    }

    const int b = bh / NHz;
    const int h = bh % NHz;
    const float inv0 = 1.f / l0;
    const float inv1 = 1.f / l1;
    const int q0 = qrow0 + gr;
#pragma unroll
    for (int nt = 0; nt < 8; ++nt) {
        const int col = nt*8 + 2*tig;
        float2 w0 = make_float2(O[nt][0]*inv0, O[nt][1]*inv0);
        float2 w1 = make_float2(O[nt][2]*inv1, O[nt][3]*inv1);
        *(float2*)&gy[((size_t)b*Tz + q0    )*Cz + h*HDz + col] = w0;
        *(float2*)&gy[((size_t)b*Tz + q0 + 8)*Cz + h*HDz + col] = w1;
    }
}

// ---------------------------------------------------------------------------
extern "C" void kernel_launch(void* const* d_in, const int* in_sizes, int n_in,
                              void* d_out, int out_size)
{
    (void)in_sizes; (void)n_in; (void)out_size;
    const float* x      = (const float*)d_in[0];
    const float* w_attn = (const float*)d_in[1];
    const float* b_attn = (const float*)d_in[2];
    const float* w_proj = (const float*)d_in[3];
    const float* b_proj = (const float*)d_in[4];
    float* out = (float*)d_out;

    float *pq, *pk, *pv, *py;
    cudaGetSymbolAddress((void**)&pq, g_q);
    cudaGetSymbolAddress((void**)&pk, g_k);
    cudaGetSymbolAddress((void**)&pv, g_v);
    cudaGetSymbolAddress((void**)&py, g_y);

    // 1) QKV = x @ w_attn + b_attn (fp16 mma), scatter q/k/v
    {
        dim3 grid(3*Cz/128, Mz/128);
        tgemm_kernel<0><<<grid, 256>>>(x, w_attn, b_attn, nullptr,
                                       Mz, 3*Cz, Cz);
    }
    // 2) Flash attention fp16 into g_y
    {
        dim3 grid(Bz*NHz, Tz/128);
        flash2_kernel<<<grid, 256>>>(pq, pk, pv, py);
    }
    // 3) out = g_y @ w_proj + b_proj (fp16 mma)
    {
        dim3 grid(Cz/128, Mz/128);
        tgemm_kernel<1><<<grid, 256>>>(py, w_proj, b_proj, out,
                                       Mz, Cz, Cz);
    }
}

// round 9
// speedup vs baseline: 2.3464x; 1.1841x over previous
#include <cuda_runtime.h>
#include <cuda_fp16.h>
#include <math.h>
#include <stdint.h>

// Problem constants
#define Bz 8
#define Tz 1024
#define Cz 768
#define NHz 12
#define HDz 64
#define Mz (Bz*Tz)        // 8192

// Scratch (device globals; no allocation). All half2-packed words.
__device__ uint32_t g_qw[Bz*NHz*Tz*HDz/2];
__device__ uint32_t g_kw[Bz*NHz*Tz*HDz/2];
__device__ uint32_t g_vw[Bz*NHz*Tz*HDz/2];
__device__ uint32_t g_yw[Bz*Tz*Cz/2];
__device__ uint32_t g_xw[Bz*Tz*Cz/2];          // x, row-major half2 (k-pairs)
__device__ uint32_t g_waw[(Cz/2)*(3*Cz)];      // w_attn, k-pair packed [384][2304]
__device__ uint32_t g_wpw[(Cz/2)*Cz];          // w_proj, k-pair packed [384][768]

__device__ __forceinline__ uint32_t pack2(float lo, float hi) {
    __half2 h = __floats2half2_rn(lo, hi);   // .x = lo (low 16 bits)
    return *reinterpret_cast<uint32_t*>(&h);
}

__device__ __forceinline__ void mma_f16(
    float& d0, float& d1, float& d2, float& d3,
    uint32_t a0, uint32_t a1, uint32_t a2, uint32_t a3,
    uint32_t b0, uint32_t b1)
{
    asm volatile(
        "mma.sync.aligned.m16n8k16.row.col.f32.f16.f16.f32 "
        "{%0,%1,%2,%3}, {%4,%5,%6,%7}, {%8,%9}, {%0,%1,%2,%3};\n"
        : "+f"(d0), "+f"(d1), "+f"(d2), "+f"(d3)
        : "r"(a0), "r"(a1), "r"(a2), "r"(a3), "r"(b0), "r"(b1));
}

// ---------------------------------------------------------------------------
// Pre-pass converters (run once per launch).
// ---------------------------------------------------------------------------
// Flat: out word i = pack2(in[2i], in[2i+1]); each thread does 4 words.
__global__ __launch_bounds__(256) void conv_flat(
    const float* __restrict__ in, uint32_t* __restrict__ out)
{
    const int t = blockIdx.x * 256 + threadIdx.x;
    const float4* p = (const float4*)in + 2*t;
    float4 lo = p[0], hi = p[1];
    uint4 w = make_uint4(pack2(lo.x, lo.y), pack2(lo.z, lo.w),
                         pack2(hi.x, hi.y), pack2(hi.z, hi.w));
    ((uint4*)out)[t] = w;
}

// K-pair pack: out[kp*N + n] = pack2(in[2kp*N + n], in[(2kp+1)*N + n]).
__global__ __launch_bounds__(256) void conv_pair(
    const float* __restrict__ in, uint32_t* __restrict__ out, int N)
{
    const int t = blockIdx.x * 256 + threadIdx.x;
    const int per = N >> 2;
    const int kp = t / per;
    const int n0 = (t - kp * per) * 4;
    float4 a = *(const float4*)(in + (size_t)(2*kp)     * N + n0);
    float4 b = *(const float4*)(in + (size_t)(2*kp + 1) * N + n0);
    uint4 w = make_uint4(pack2(a.x, b.x), pack2(a.y, b.y),
                         pack2(a.z, b.z), pack2(a.w, b.w));
    *(uint4*)(out + (size_t)kp * N + n0) = w;
}

// ---------------------------------------------------------------------------
// FP16 GEMM on half2-word operands: 128x128 CTA, K-stage 32 halves (16 words),
// fragment-major smem, 1 sync/stage, 2 CTAs/SM. Producers are pure word moves.
// ---------------------------------------------------------------------------
#define AFW 2112   // 16 tiles * 132 words
#define BFW 2112   // 32 tiles * 66 words

template <int EPI>
__global__ __launch_bounds__(256, 2) void tgemm_kernel(
    const uint32_t* __restrict__ Aw, const uint32_t* __restrict__ Bw,
    const float* __restrict__ bias, float* __restrict__ Cout,
    int M, int N, int K)
{
    __shared__ __align__(16) uint32_t Afr[2][AFW];
    __shared__ __align__(16) uint32_t Bfr[2][BFW];

    const int tid  = threadIdx.x;
    const int wid  = tid >> 5;
    const int lane = tid & 31;
    const int wm   = wid & 1;
    const int wn   = wid >> 1;
    const int gr   = lane >> 2;
    const int tig  = lane & 3;
    const int bm   = blockIdx.y * 128;
    const int bn   = blockIdx.x * 128;
    const int Kw   = K >> 1;   // words per A row

    // ---- Producer geometry ----
    const int ar0 = tid >> 2;            // 0..63
    const int kw0 = (tid & 3) * 4;       // word offset 0,4,8,12
    const int pks = kw0 >> 3;
    const int pkh = (kw0 >> 2) & 1;
    const int agr = ar0 & 7;
    const int ag2 = (agr >> 1) & 3;
    const int awb0 = ((ar0      >> 4)*2 + pks)*132 + agr*16 + pkh*2 + ((ar0 >> 3) & 1);
    const int awb1 = (((ar0+64) >> 4)*2 + pks)*132 + agr*16 + pkh*2 + (((ar0+64) >> 3) & 1);
    const int bk   = tid >> 5;           // 0..7 (k-pair row)
    const int bn0  = (tid & 31) * 4;
    const int btig = bk & 3;
    const int bkh  = (bk >> 2) & 1;
    const int bcom = (bn0 >> 3)*66 + ((bn0 & 7)*4 + btig)*2 + bkh;
    const int bwb0 = bcom;
    const int bwb1 = 16*66 + bcom;

    const uint32_t* Ap0 = Aw + (size_t)(bm + ar0)      * Kw + kw0;
    const uint32_t* Ap1 = Aw + (size_t)(bm + ar0 + 64) * Kw + kw0;
    const uint32_t* Bp0 = Bw + (size_t)bk       * N + bn + bn0;
    const uint32_t* Bp1 = Bw + (size_t)(bk + 8) * N + bn + bn0;

    const int aswz  = (lane ^ ((lane >> 3) & 3)) * 4;
    const int boff2 = lane * 2;

    float acc[4][4][4];
#pragma unroll
    for (int i = 0; i < 4; ++i)
#pragma unroll
        for (int j = 0; j < 4; ++j)
#pragma unroll
            for (int r = 0; r < 4; ++r) acc[i][j][r] = 0.f;

    const int nstages = K / 32;   // 24

    // ---- Prologue: stage 0 -> buf 0 ----
    {
        uint4 a0 = *(const uint4*)(Ap0);
        uint4 a1 = *(const uint4*)(Ap1);
        uint4 b0 = *(const uint4*)(Bp0);
        uint4 b1 = *(const uint4*)(Bp1);
        uint32_t* Au = Afr[0];
        uint32_t* Bu = Bfr[0];
        Au[awb0 + ((0^ag2)<<2)] = a0.x;
        Au[awb0 + ((1^ag2)<<2)] = a0.y;
        Au[awb0 + ((2^ag2)<<2)] = a0.z;
        Au[awb0 + ((3^ag2)<<2)] = a0.w;
        Au[awb1 + ((0^ag2)<<2)] = a1.x;
        Au[awb1 + ((1^ag2)<<2)] = a1.y;
        Au[awb1 + ((2^ag2)<<2)] = a1.z;
        Au[awb1 + ((3^ag2)<<2)] = a1.w;
        Bu[bwb0     ] = b0.x;
        Bu[bwb0 +  8] = b0.y;
        Bu[bwb0 + 16] = b0.z;
        Bu[bwb0 + 24] = b0.w;
        Bu[bwb1     ] = b1.x;
        Bu[bwb1 +  8] = b1.y;
        Bu[bwb1 + 16] = b1.z;
        Bu[bwb1 + 24] = b1.w;
    }
    __syncthreads();

    for (int s = 0; s < nstages; ++s) {
        const int buf = s & 1;
        const bool more = (s + 1 < nstages);

        uint4 a0, a1, b0, b1;
        if (more) {
            const int ko = (s + 1) * 16;             // word offset in A row
            a0 = *(const uint4*)(Ap0 + ko);
            a1 = *(const uint4*)(Ap1 + ko);
            const size_t bo = (size_t)(s + 1) * 16 * N;  // 16 k-pair rows
            b0 = *(const uint4*)(Bp0 + bo);
            b1 = *(const uint4*)(Bp1 + bo);
        }

        // ---- Consume buf: 2 k16-steps x 16 mma ----
        const uint32_t* Af = Afr[buf];
        const uint32_t* Bf = Bfr[buf];
#pragma unroll
        for (int ks = 0; ks < 2; ++ks) {
            uint4 af[4];
#pragma unroll
            for (int mt = 0; mt < 4; ++mt)
                af[mt] = *(const uint4*)&Af[((wm*4 + mt)*2 + ks)*132 + aswz];
            uint2 bf[4];
#pragma unroll
            for (int nt = 0; nt < 4; ++nt)
                bf[nt] = *(const uint2*)&Bf[(ks*16 + wn*4 + nt)*66 + boff2];
#pragma unroll
            for (int mt = 0; mt < 4; ++mt)
#pragma unroll
                for (int nt = 0; nt < 4; ++nt)
                    mma_f16(acc[mt][nt][0], acc[mt][nt][1],
                            acc[mt][nt][2], acc[mt][nt][3],
                            af[mt].x, af[mt].y, af[mt].z, af[mt].w,
                            bf[nt].x, bf[nt].y);
        }

        // ---- Produce buf^1 ----
        if (more) {
            uint32_t* Au = Afr[buf ^ 1];
            uint32_t* Bu = Bfr[buf ^ 1];
            Au[awb0 + ((0^ag2)<<2)] = a0.x;
            Au[awb0 + ((1^ag2)<<2)] = a0.y;
            Au[awb0 + ((2^ag2)<<2)] = a0.z;
            Au[awb0 + ((3^ag2)<<2)] = a0.w;
            Au[awb1 + ((0^ag2)<<2)] = a1.x;
            Au[awb1 + ((1^ag2)<<2)] = a1.y;
            Au[awb1 + ((2^ag2)<<2)] = a1.z;
            Au[awb1 + ((3^ag2)<<2)] = a1.w;
            Bu[bwb0     ] = b0.x;
            Bu[bwb0 +  8] = b0.y;
            Bu[bwb0 + 16] = b0.z;
            Bu[bwb0 + 24] = b0.w;
            Bu[bwb1     ] = b1.x;
            Bu[bwb1 +  8] = b1.y;
            Bu[bwb1 + 16] = b1.z;
            Bu[bwb1 + 24] = b1.w;
        }
        __syncthreads();
    }

    // ---- Epilogue ----
#pragma unroll
    for (int mt = 0; mt < 4; ++mt) {
#pragma unroll
        for (int nt = 0; nt < 4; ++nt) {
            const int nb2 = bn + wn*32 + nt*8 + 2*tig;
#pragma unroll
            for (int half = 0; half < 2; ++half) {
                const int m = bm + wm*64 + mt*16 + gr + half*8;
                const float v0 = acc[mt][nt][half*2 + 0] + bias[nb2 + 0];
                const float v1 = acc[mt][nt][half*2 + 1] + bias[nb2 + 1];
                if (EPI == 0) {
                    const int which = nb2 / Cz;
                    const int c = nb2 - which * Cz;
                    const int h = c >> 6;
                    const int d = c & 63;            // even
                    const int b = m >> 10;
                    const int t = m & 1023;
                    uint32_t* dst = (which == 0) ? g_qw : (which == 1) ? g_kw : g_vw;
                    dst[(((size_t)(b*NHz + h) << 10) + t)*32 + (d >> 1)] = pack2(v0, v1);
                } else {
                    float2 val = make_float2(v0, v1);
                    *(float2*)&Cout[(size_t)m*N + nb2] = val;
                }
            }
        }
    }
}

// ---------------------------------------------------------------------------
// Flash attention fp16 on half2-word q/k/v (row stride 32 words).
// Staging is pure word moves (V transpose via byte_perm). Writes g_yw half2.
// ---------------------------------------------------------------------------
#define KWS 36
#define VWS 72
#define KTW (64*KWS)
#define VTW (32*VWS)

__global__ __launch_bounds__(256) void flash2_kernel(
    const uint32_t* __restrict__ gq, const uint32_t* __restrict__ gk,
    const uint32_t* __restrict__ gv, uint32_t* __restrict__ gy)
{
    __shared__ __align__(16) uint32_t Kw[2][KTW];
    __shared__ __align__(16) uint32_t Vw[2][VTW];

    const int bh  = blockIdx.x;
    const int qb  = 7 - blockIdx.y;
    const int tid = threadIdx.x;
    const int wid = tid >> 5, lane = tid & 31;
    const int gr  = lane >> 2;
    const int tig = lane & 3;

    const int qrow0 = qb*128 + wid*16;
    const float scale = 0.125f;

    // ---- Q fragments: direct word loads ----
    const uint32_t* qw = gq + ((size_t)bh*Tz + qrow0) * 32;
    uint32_t qf[4][4];
#pragma unroll
    for (int kb = 0; kb < 4; ++kb) {
        qf[kb][0] = qw[(size_t)gr*32     + kb*8 + tig    ];
        qf[kb][1] = qw[(size_t)(gr+8)*32 + kb*8 + tig    ];
        qf[kb][2] = qw[(size_t)gr*32     + kb*8 + tig + 4];
        qf[kb][3] = qw[(size_t)(gr+8)*32 + kb*8 + tig + 4];
    }

    float O[8][4];
#pragma unroll
    for (int nt = 0; nt < 8; ++nt)
#pragma unroll
        for (int r = 0; r < 4; ++r) O[nt][r] = 0.f;
    float m0 = -INFINITY, m1 = -INFINITY, l0 = 0.f, l1 = 0.f;

    const int ntiles = 2*qb + 2;

    // staging geometry
    const int sr  = tid >> 2;            // K: key row 0..63
    const int sdw = (tid & 3) * 8;       // K: word offset 0,8,16,24
    const int vp  = tid >> 3;            // V: key-pair 0..31
    const int vdc = (tid & 7) * 8;       // V: d cols vdc..vdc+7 (words vdc..+7 out)
    const uint32_t* kbase0 = gk + (size_t)bh*Tz*32;
    const uint32_t* vbase0 = gv + (size_t)bh*Tz*32;

    // ---- Prologue: tile 0 -> buf 0 ----
    {
        const uint32_t* kp = kbase0 + (size_t)sr*32 + sdw;
        *(uint4*)&Kw[0][sr*KWS + sdw    ] = *(const uint4*)(kp);
        *(uint4*)&Kw[0][sr*KWS + sdw + 4] = *(const uint4*)(kp + 4);

        const uint32_t* vpl = vbase0 + (size_t)(2*vp)*32 + (vdc >> 1);
        uint4 u0 = *(const uint4*)(vpl);
        uint4 u1 = *(const uint4*)(vpl + 32);
        uint4 wA = make_uint4(__byte_perm(u0.x, u1.x, 0x5410),
                              __byte_perm(u0.x, u1.x, 0x7632),
                              __byte_perm(u0.y, u1.y, 0x5410),
                              __byte_perm(u0.y, u1.y, 0x7632));
        uint4 wB = make_uint4(__byte_perm(u0.z, u1.z, 0x5410),
                              __byte_perm(u0.z, u1.z, 0x7632),
                              __byte_perm(u0.w, u1.w, 0x5410),
                              __byte_perm(u0.w, u1.w, 0x7632));
        *(uint4*)&Vw[0][vp*VWS + vdc    ] = wA;
        *(uint4*)&Vw[0][vp*VWS + vdc + 4] = wB;
    }
    __syncthreads();

    for (int kt = 0; kt < ntiles; ++kt) {
        const int cur = kt & 1;
        const bool more = (kt + 1 < ntiles);

        // Prefetch next tile to registers (4 uint4)
        uint4 ka, kb2, u0, u1;
        if (more) {
            const uint32_t* kp = kbase0 + ((size_t)(kt+1)*64 + sr)*32 + sdw;
            ka  = *(const uint4*)(kp);
            kb2 = *(const uint4*)(kp + 4);
            const uint32_t* vpl = vbase0 + ((size_t)(kt+1)*64 + 2*vp)*32 + (vdc >> 1);
            u0 = *(const uint4*)(vpl);
            u1 = *(const uint4*)(vpl + 32);
        }

        if (kt*64 <= qrow0 + 15) {
            const uint32_t* Ksb = Kw[cur];
            const uint32_t* Vsb = Vw[cur];

            float sacc[8][4];
#pragma unroll
            for (int nt = 0; nt < 8; ++nt)
#pragma unroll
                for (int r = 0; r < 4; ++r) sacc[nt][r] = 0.f;

#pragma unroll
            for (int kb = 0; kb < 4; ++kb) {
#pragma unroll
                for (int nt = 0; nt < 8; ++nt) {
                    uint32_t b0 = Ksb[(nt*8 + gr)*KWS + kb*8 + tig    ];
                    uint32_t b1 = Ksb[(nt*8 + gr)*KWS + kb*8 + tig + 4];
                    mma_f16(sacc[nt][0], sacc[nt][1], sacc[nt][2], sacc[nt][3],
                            qf[kb][0], qf[kb][1], qf[kb][2], qf[kb][3],
                            b0, b1);
                }
            }

            const bool bnd = (kt*64 + 63 > qrow0);
            if (bnd) {
                const int r0 = qrow0 + gr, r1 = qrow0 + gr + 8;
#pragma unroll
                for (int nt = 0; nt < 8; ++nt) {
                    const int c0 = kt*64 + nt*8 + 2*tig;
                    sacc[nt][0] = (c0     > r0) ? -1e30f : sacc[nt][0]*scale;
                    sacc[nt][1] = (c0 + 1 > r0) ? -1e30f : sacc[nt][1]*scale;
                    sacc[nt][2] = (c0     > r1) ? -1e30f : sacc[nt][2]*scale;
                    sacc[nt][3] = (c0 + 1 > r1) ? -1e30f : sacc[nt][3]*scale;
                }
            } else {
#pragma unroll
                for (int nt = 0; nt < 8; ++nt)
#pragma unroll
                    for (int r = 0; r < 4; ++r) sacc[nt][r] *= scale;
            }

            float mx0 = -INFINITY, mx1 = -INFINITY;
#pragma unroll
            for (int nt = 0; nt < 8; ++nt) {
                mx0 = fmaxf(mx0, fmaxf(sacc[nt][0], sacc[nt][1]));
                mx1 = fmaxf(mx1, fmaxf(sacc[nt][2], sacc[nt][3]));
            }
            mx0 = fmaxf(mx0, __shfl_xor_sync(0xffffffffu, mx0, 1));
            mx0 = fmaxf(mx0, __shfl_xor_sync(0xffffffffu, mx0, 2));
            mx1 = fmaxf(mx1, __shfl_xor_sync(0xffffffffu, mx1, 1));
            mx1 = fmaxf(mx1, __shfl_xor_sync(0xffffffffu, mx1, 2));

            const float mn0 = fmaxf(m0, mx0);
            const float mn1 = fmaxf(m1, mx1);
            const float a0 = __expf(m0 - mn0);
            const float a1 = __expf(m1 - mn1);
            m0 = mn0; m1 = mn1;

            float s0 = 0.f, s1 = 0.f;
#pragma unroll
            for (int nt = 0; nt < 8; ++nt) {
                sacc[nt][0] = __expf(sacc[nt][0] - mn0);
                sacc[nt][1] = __expf(sacc[nt][1] - mn0);
                sacc[nt][2] = __expf(sacc[nt][2] - mn1);
                sacc[nt][3] = __expf(sacc[nt][3] - mn1);
                s0 += sacc[nt][0] + sacc[nt][1];
                s1 += sacc[nt][2] + sacc[nt][3];
            }
            s0 += __shfl_xor_sync(0xffffffffu, s0, 1);
            s0 += __shfl_xor_sync(0xffffffffu, s0, 2);
            s1 += __shfl_xor_sync(0xffffffffu, s1, 1);
            s1 += __shfl_xor_sync(0xffffffffu, s1, 2);
            l0 = l0*a0 + s0;
            l1 = l1*a1 + s1;

#pragma unroll
            for (int nt = 0; nt < 8; ++nt) {
                O[nt][0] *= a0;  O[nt][1] *= a0;
                O[nt][2] *= a1;  O[nt][3] *= a1;
            }

#pragma unroll
            for (int kb = 0; kb < 4; ++kb) {
                const uint32_t pa0 = pack2(sacc[2*kb  ][0], sacc[2*kb  ][1]);
                const uint32_t pa1 = pack2(sacc[2*kb  ][2], sacc[2*kb  ][3]);
                const uint32_t pa2 = pack2(sacc[2*kb+1][0], sacc[2*kb+1][1]);
                const uint32_t pa3 = pack2(sacc[2*kb+1][2], sacc[2*kb+1][3]);
#pragma unroll
                for (int nt = 0; nt < 8; ++nt) {
                    uint32_t b0 = Vsb[(kb*8 + tig    )*VWS + nt*8 + gr];
                    uint32_t b1 = Vsb[(kb*8 + tig + 4)*VWS + nt*8 + gr];
                    mma_f16(O[nt][0], O[nt][1], O[nt][2], O[nt][3],
                            pa0, pa1, pa2, pa3, b0, b1);
                }
            }
        }

        if (more) {
            const int nb = cur ^ 1;
            *(uint4*)&Kw[nb][sr*KWS + sdw    ] = ka;
            *(uint4*)&Kw[nb][sr*KWS + sdw + 4] = kb2;
            uint4 wA = make_uint4(__byte_perm(u0.x, u1.x, 0x5410),
                                  __byte_perm(u0.x, u1.x, 0x7632),
                                  __byte_perm(u0.y, u1.y, 0x5410),
                                  __byte_perm(u0.y, u1.y, 0x7632));
            uint4 wB = make_uint4(__byte_perm(u0.z, u1.z, 0x5410),
                                  __byte_perm(u0.z, u1.z, 0x7632),
                                  __byte_perm(u0.w, u1.w, 0x5410),
                                  __byte_perm(u0.w, u1.w, 0x7632));
            *(uint4*)&Vw[nb][vp*VWS + vdc    ] = wA;
            *(uint4*)&Vw[nb][vp*VWS + vdc + 4] = wB;
        }
        __syncthreads();
    }

    // ---- Epilogue: normalize, pack to half2, write g_yw ----
    const int b = bh / NHz;
    const int h = bh % NHz;
    const float inv0 = 1.f / l0;
    const float inv1 = 1.f / l1;
    const int q0 = qrow0 + gr;
#pragma unroll
    for (int nt = 0; nt < 8; ++nt) {
        const int wcol = h*32 + nt*4 + tig;   // word column in [384]
        gy[((size_t)b*Tz + q0    )*384 + wcol] = pack2(O[nt][0]*inv0, O[nt][1]*inv0);
        gy[((size_t)b*Tz + q0 + 8)*384 + wcol] = pack2(O[nt][2]*inv1, O[nt][3]*inv1);
    }
}

// ---------------------------------------------------------------------------
extern "C" void kernel_launch(void* const* d_in, const int* in_sizes, int n_in,
                              void* d_out, int out_size)
{
    (void)in_sizes; (void)n_in; (void)out_size;
    const float* x      = (const float*)d_in[0];
    const float* w_attn = (const float*)d_in[1];
    const float* b_attn = (const float*)d_in[2];
    const float* w_proj = (const float*)d_in[3];
    const float* b_proj = (const float*)d_in[4];
    float* out = (float*)d_out;

    uint32_t *pq, *pk, *pv, *py, *px, *pwa, *pwp;
    cudaGetSymbolAddress((void**)&pq,  g_qw);
    cudaGetSymbolAddress((void**)&pk,  g_kw);
    cudaGetSymbolAddress((void**)&pv,  g_vw);
    cudaGetSymbolAddress((void**)&py,  g_yw);
    cudaGetSymbolAddress((void**)&px,  g_xw);
    cudaGetSymbolAddress((void**)&pwa, g_waw);
    cudaGetSymbolAddress((void**)&pwp, g_wpw);

    // 0) Pre-pass: convert x / w_attn / w_proj to half2 words
    conv_flat<<<3072, 256>>>(x, px);                 // 8*1024*768/2/4 = 786432 thr
    conv_pair<<<864, 256>>>(w_attn, pwa, 3*Cz);      // 384*2304/4 = 221184 thr
    conv_pair<<<288, 256>>>(w_proj, pwp, Cz);        // 384*768/4  =  73728 thr

    // 1) QKV = x @ w_attn + b_attn (fp16 words), scatter half2 q/k/v
    {
        dim3 grid(3*Cz/128, Mz/128);
        tgemm_kernel<0><<<grid, 256>>>(px, pwa, b_attn, nullptr,
                                       Mz, 3*Cz, Cz);
    }
    // 2) Flash attention fp16 into g_yw (half2)
    {
        dim3 grid(Bz*NHz, Tz/128);
        flash2_kernel<<<grid, 256>>>(pq, pk, pv, py);
    }
    // 3) out = g_y @ w_proj + b_proj (fp16 words, f32 out)
    {
        dim3 grid(Cz/128, Mz/128);
        tgemm_kernel<1><<<grid, 256>>>(py, pwp, b_proj, out,
                                       Mz, Cz, Cz);
    }
}

// round 12
// speedup vs baseline: 2.3676x; 1.0090x over previous
#include <cuda_runtime.h>
#include <cuda_fp16.h>
#include <math.h>
#include <stdint.h>

// Problem constants
#define Bz 8
#define Tz 1024
#define Cz 768
#define NHz 12
#define HDz 64
#define Mz (Bz*Tz)        // 8192
#define KWz (Cz/2)        // 384 words per row
#define NSTG 24           // 768 / 32 halves per stage

// Scratch (device globals; no allocation).
__device__ uint32_t g_qw[Bz*NHz*Tz*HDz/2];      // q row-major half2 words
__device__ uint32_t g_kw[Bz*NHz*Tz*HDz/2];
__device__ uint32_t g_vw[Bz*NHz*Tz*HDz/2];
__device__ uint32_t g_xf[64*NSTG*2048];          // x, A-fragment-major blocks
__device__ uint32_t g_yf[64*NSTG*2048];          // y, A-fragment-major blocks
__device__ uint32_t g_waf[18*NSTG*2048];         // w_attn, B-fragment-major
__device__ uint32_t g_wpf[6*NSTG*2048];          // w_proj, B-fragment-major

__device__ __forceinline__ uint32_t pack2(float lo, float hi) {
    __half2 h = __floats2half2_rn(lo, hi);
    return *reinterpret_cast<uint32_t*>(&h);
}

__device__ __forceinline__ void mma_f16(
    float& d0, float& d1, float& d2, float& d3,
    uint32_t a0, uint32_t a1, uint32_t a2, uint32_t a3,
    uint32_t b0, uint32_t b1)
{
    asm volatile(
        "mma.sync.aligned.m16n8k16.row.col.f32.f16.f16.f32 "
        "{%0,%1,%2,%3}, {%4,%5,%6,%7}, {%8,%9}, {%0,%1,%2,%3};\n"
        : "+f"(d0), "+f"(d1), "+f"(d2), "+f"(d3)
        : "r"(a0), "r"(a1), "r"(a2), "r"(a3), "r"(b0), "r"(b1));
}

__device__ __forceinline__ uint32_t smem_u32(const void* p) {
    uint32_t a;
    asm("{ .reg .u64 t; cvta.to.shared.u64 t, %1; cvt.u32.u64 %0, t; }"
        : "=r"(a) : "l"(p));
    return a;
}

__device__ __forceinline__ void cp16(uint32_t dst, const uint32_t* src) {
    asm volatile("cp.async.ca.shared.global [%0], [%1], 16;\n"
                 :: "r"(dst), "l"(src));
}
#define CP_COMMIT() asm volatile("cp.async.commit_group;\n" ::: "memory")
#define CP_WAIT(n)  asm volatile("cp.async.wait_group %0;\n" :: "n"(n) : "memory")

// ---------------------------------------------------------------------------
// Pre-pass: build fragment-major gmem images.
// A block (bm, s): 16 tiles x 128 words; word = T*128 + swz(lane)*4 + w
//   T = mtile(0..7)*2 + ks; a0..a3 = (gr,tig),(gr+8,tig),(gr,tig+4),(gr+8,tig+4)
// B block (bn, s): 32 tiles x 64 words; T2 = ks*16 + ntile; word = lane*2 + w
// ---------------------------------------------------------------------------
__global__ __launch_bounds__(256) void conv_xf(
    const float* __restrict__ x, uint32_t* __restrict__ out)
{
    const int t = blockIdx.x * 256 + threadIdx.x;   // uint4 index
    const int u = t & 511, block = t >> 9;
    const int T = u >> 5, lanep = u & 31;
    const int lane = lanep ^ ((lanep >> 3) & 3);
    const int gr = lane >> 2, tig = lane & 3;
    const int mt = T >> 1, ks = T & 1;
    const int bm = block / NSTG, s = block - bm * NSTG;
    const int m0 = bm*128 + mt*16 + gr;
    const int kw = s*16 + ks*8 + tig;
    const float* r0 = x + (size_t)m0 * Cz;
    const float* r8 = r0 + 8 * Cz;
    float2 a = *(const float2*)(r0 + 2*kw);
    float2 b = *(const float2*)(r8 + 2*kw);
    float2 c = *(const float2*)(r0 + 2*kw + 8);
    float2 d = *(const float2*)(r8 + 2*kw + 8);
    uint4 w = make_uint4(pack2(a.x, a.y), pack2(b.x, b.y),
                         pack2(c.x, c.y), pack2(d.x, d.y));
    ((uint4*)out)[t] = w;
}

__global__ __launch_bounds__(256) void conv_wf(
    const float* __restrict__ W, uint32_t* __restrict__ out, int N)
{
    const int t = blockIdx.x * 256 + threadIdx.x;   // uint2 index
    const int u = t & 1023, block = t >> 10;
    const int T2 = u >> 5, lane = u & 31;
    const int ks = T2 >> 4, ntile = T2 & 15;
    const int gn = lane >> 2, tig = lane & 3;
    const int bn = block / NSTG, s = block - bn * NSTG;
    const int n = bn*128 + ntile*8 + gn;
    const int kw = s*16 + ks*8 + tig;
    uint2 w;
    w.x = pack2(W[(size_t)(2*kw    )*N + n], W[(size_t)(2*kw + 1)*N + n]);
    w.y = pack2(W[(size_t)(2*kw + 8)*N + n], W[(size_t)(2*kw + 9)*N + n]);
    ((uint2*)out)[t] = w;
}

// ---------------------------------------------------------------------------
// FP16 GEMM: 128x128 CTA, 3-buffer cp.async.ca pipeline (1 bar/stage),
// fragment-major gmem -> producer is 4x cp16/thread/stage, zero STS.
// ---------------------------------------------------------------------------
#define GS_WORDS (6*2048)   // 48 KB dynamic smem

template <int EPI>
__global__ __launch_bounds__(256, 2) void tgemm_kernel(
    const uint32_t* __restrict__ Af, const uint32_t* __restrict__ Bf,
    const float* __restrict__ bias, float* __restrict__ Cout, int N)
{
    extern __shared__ uint32_t sm[];

    const int tid  = threadIdx.x;
    const int wid  = tid >> 5;
    const int lane = tid & 31;
    const int wm   = wid & 1;
    const int wn   = wid >> 1;
    const int gr   = lane >> 2;
    const int tig  = lane & 3;
    const int bm   = blockIdx.y * 128;
    const int bn   = blockIdx.x * 128;

    const uint32_t ab = smem_u32(sm) + tid*32;          // +tid*8 words
    const uint32_t bb = ab + 3*2048*4;
    const uint32_t* Abase = Af + (size_t)blockIdx.y * NSTG * 2048 + tid*8;
    const uint32_t* Bbase = Bf + (size_t)blockIdx.x * NSTG * 2048 + tid*8;

    const int aswz = (lane ^ ((lane >> 3) & 3)) * 4;
    const int boff = lane * 2;

    float acc[4][4][4];
#pragma unroll
    for (int i = 0; i < 4; ++i)
#pragma unroll
        for (int j = 0; j < 4; ++j)
#pragma unroll
            for (int r = 0; r < 4; ++r) acc[i][j][r] = 0.f;

    // Prologue: issue stages 0 and 1
#pragma unroll
    for (int p = 0; p < 2; ++p) {
        const uint32_t ad = ab + p*2048*4;
        const uint32_t bd = bb + p*2048*4;
        cp16(ad,      Abase + p*2048);
        cp16(ad + 16, Abase + p*2048 + 4);
        cp16(bd,      Bbase + p*2048);
        cp16(bd + 16, Bbase + p*2048 + 4);
        CP_COMMIT();
    }

    for (int s = 0; s < NSTG; ++s) {
        if (s < NSTG - 1) CP_WAIT(1); else CP_WAIT(0);
        __syncthreads();

        const int buf = s % 3;
        const uint32_t* Ab = sm + buf*2048;
        const uint32_t* Bb = sm + 3*2048 + buf*2048;

#pragma unroll
        for (int ks = 0; ks < 2; ++ks) {
            uint4 af[4];
#pragma unroll
            for (int mt = 0; mt < 4; ++mt)
                af[mt] = *(const uint4*)&Ab[((wm*4 + mt)*2 + ks)*128 + aswz];
            uint2 bf[4];
#pragma unroll
            for (int nt = 0; nt < 4; ++nt)
                bf[nt] = *(const uint2*)&Bb[(ks*16 + wn*4 + nt)*64 + boff];
#pragma unroll
            for (int mt = 0; mt < 4; ++mt)
#pragma unroll
                for (int nt = 0; nt < 4; ++nt)
                    mma_f16(acc[mt][nt][0], acc[mt][nt][1],
                            acc[mt][nt][2], acc[mt][nt][3],
                            af[mt].x, af[mt].y, af[mt].z, af[mt].w,
                            bf[nt].x, bf[nt].y);
        }

        if (s + 2 < NSTG) {
            // overwrites buf consumed at iter s-1; all threads passed this
            // iteration's barrier after that consume -> race-free
            const int nb = (s + 2) % 3;
            const uint32_t ad = ab + nb*2048*4;
            const uint32_t bd = bb + nb*2048*4;
            cp16(ad,      Abase + (s + 2)*2048);
            cp16(ad + 16, Abase + (s + 2)*2048 + 4);
            cp16(bd,      Bbase + (s + 2)*2048);
            cp16(bd + 16, Bbase + (s + 2)*2048 + 4);
            CP_COMMIT();
        }
    }

    // ---- Epilogue (identical numerics to R9) ----
#pragma unroll
    for (int mt = 0; mt < 4; ++mt) {
#pragma unroll
        for (int nt = 0; nt < 4; ++nt) {
            const int nb2 = bn + wn*32 + nt*8 + 2*tig;
#pragma unroll
            for (int half = 0; half < 2; ++half) {
                const int m = bm + wm*64 + mt*16 + gr + half*8;
                const float v0 = acc[mt][nt][half*2 + 0] + bias[nb2 + 0];
                const float v1 = acc[mt][nt][half*2 + 1] + bias[nb2 + 1];
                if (EPI == 0) {
                    const int which = nb2 / Cz;
                    const int c = nb2 - which * Cz;
                    const int h = c >> 6;
                    const int d = c & 63;
                    const int b = m >> 10;
                    const int t = m & 1023;
                    uint32_t* dst = (which == 0) ? g_qw : (which == 1) ? g_kw : g_vw;
                    dst[(((size_t)(b*NHz + h) << 10) + t)*32 + (d >> 1)] = pack2(v0, v1);
                } else {
                    *(float2*)&Cout[(size_t)m*N + nb2] = make_float2(v0, v1);
                }
            }
        }
    }
}

// ---------------------------------------------------------------------------
// Flash attention fp16 (R9 body); epilogue writes g_yf in A-fragment-major
// layout so tgemm<1>'s producer is pure cp.async.
// ---------------------------------------------------------------------------
#define KWS 36
#define VWS 72
#define KTW (64*KWS)
#define VTW (32*VWS)

__global__ __launch_bounds__(256) void flash2_kernel(
    const uint32_t* __restrict__ gq, const uint32_t* __restrict__ gk,
    const uint32_t* __restrict__ gv, uint32_t* __restrict__ gy)
{
    __shared__ __align__(16) uint32_t Kw[2][KTW];
    __shared__ __align__(16) uint32_t Vw[2][VTW];

    const int bh  = blockIdx.x;
    const int qb  = 7 - blockIdx.y;
    const int tid = threadIdx.x;
    const int wid = tid >> 5, lane = tid & 31;
    const int gr  = lane >> 2;
    const int tig = lane & 3;

    const int qrow0 = qb*128 + wid*16;
    const float scale = 0.125f;

    const uint32_t* qw = gq + ((size_t)bh*Tz + qrow0) * 32;
    uint32_t qf[4][4];
#pragma unroll
    for (int kb = 0; kb < 4; ++kb) {
        qf[kb][0] = qw[(size_t)gr*32     + kb*8 + tig    ];
        qf[kb][1] = qw[(size_t)(gr+8)*32 + kb*8 + tig    ];
        qf[kb][2] = qw[(size_t)gr*32     + kb*8 + tig + 4];
        qf[kb][3] = qw[(size_t)(gr+8)*32 + kb*8 + tig + 4];
    }

    float O[8][4];
#pragma unroll
    for (int nt = 0; nt < 8; ++nt)
#pragma unroll
        for (int r = 0; r < 4; ++r) O[nt][r] = 0.f;
    float m0 = -INFINITY, m1 = -INFINITY, l0 = 0.f, l1 = 0.f;

    const int ntiles = 2*qb + 2;

    const int sr  = tid >> 2;
    const int sdw = (tid & 3) * 8;
    const int vp  = tid >> 3;
    const int vdc = (tid & 7) * 8;
    const uint32_t* kbase0 = gk + (size_t)bh*Tz*32;
    const uint32_t* vbase0 = gv + (size_t)bh*Tz*32;

    {
        const uint32_t* kp = kbase0 + (size_t)sr*32 + sdw;
        *(uint4*)&Kw[0][sr*KWS + sdw    ] = *(const uint4*)(kp);
        *(uint4*)&Kw[0][sr*KWS + sdw + 4] = *(const uint4*)(kp + 4);

        const uint32_t* vpl = vbase0 + (size_t)(2*vp)*32 + (vdc >> 1);
        uint4 u0 = *(const uint4*)(vpl);
        uint4 u1 = *(const uint4*)(vpl + 32);
        uint4 wA = make_uint4(__byte_perm(u0.x, u1.x, 0x5410),
                              __byte_perm(u0.x, u1.x, 0x7632),
                              __byte_perm(u0.y, u1.y, 0x5410),
                              __byte_perm(u0.y, u1.y, 0x7632));
        uint4 wB = make_uint4(__byte_perm(u0.z, u1.z, 0x5410),
                              __byte_perm(u0.z, u1.z, 0x7632),
                              __byte_perm(u0.w, u1.w, 0x5410),
                              __byte_perm(u0.w, u1.w, 0x7632));
        *(uint4*)&Vw[0][vp*VWS + vdc    ] = wA;
        *(uint4*)&Vw[0][vp*VWS + vdc + 4] = wB;
    }
    __syncthreads();

    for (int kt = 0; kt < ntiles; ++kt) {
        const int cur = kt & 1;
        const bool more = (kt + 1 < ntiles);

        uint4 ka, kb2, u0, u1;
        if (more) {
            const uint32_t* kp = kbase0 + ((size_t)(kt+1)*64 + sr)*32 + sdw;
            ka  = *(const uint4*)(kp);
            kb2 = *(const uint4*)(kp + 4);
            const uint32_t* vpl = vbase0 + ((size_t)(kt+1)*64 + 2*vp)*32 + (vdc >> 1);
            u0 = *(const uint4*)(vpl);
            u1 = *(const uint4*)(vpl + 32);
        }

        if (kt*64 <= qrow0 + 15) {
            const uint32_t* Ksb = Kw[cur];
            const uint32_t* Vsb = Vw[cur];

            float sacc[8][4];
#pragma unroll
            for (int nt = 0; nt < 8; ++nt)
#pragma unroll
                for (int r = 0; r < 4; ++r) sacc[nt][r] = 0.f;

#pragma unroll
            for (int kb = 0; kb < 4; ++kb) {
#pragma unroll
                for (int nt = 0; nt < 8; ++nt) {
                    uint32_t b0 = Ksb[(nt*8 + gr)*KWS + kb*8 + tig    ];
                    uint32_t b1 = Ksb[(nt*8 + gr)*KWS + kb*8 + tig + 4];
                    mma_f16(sacc[nt][0], sacc[nt][1], sacc[nt][2], sacc[nt][3],
                            qf[kb][0], qf[kb][1], qf[kb][2], qf[kb][3],
                            b0, b1);
                }
            }

            const bool bnd = (kt*64 + 63 > qrow0);
            if (bnd) {
                const int r0 = qrow0 + gr, r1 = qrow0 + gr + 8;
#pragma unroll
                for (int nt = 0; nt < 8; ++nt) {
                    const int c0 = kt*64 + nt*8 + 2*tig;
                    sacc[nt][0] = (c0     > r0) ? -1e30f : sacc[nt][0]*scale;
                    sacc[nt][1] = (c0 + 1 > r0) ? -1e30f : sacc[nt][1]*scale;
                    sacc[nt][2] = (c0     > r1) ? -1e30f : sacc[nt][2]*scale;
                    sacc[nt][3] = (c0 + 1 > r1) ? -1e30f : sacc[nt][3]*scale;
                }
            } else {
#pragma unroll
                for (int nt = 0; nt < 8; ++nt)
#pragma unroll
                    for (int r = 0; r < 4; ++r) sacc[nt][r] *= scale;
            }

            float mx0 = -INFINITY, mx1 = -INFINITY;
#pragma unroll
            for (int nt = 0; nt < 8; ++nt) {
                mx0 = fmaxf(mx0, fmaxf(sacc[nt][0], sacc[nt][1]));
                mx1 = fmaxf(mx1, fmaxf(sacc[nt][2], sacc[nt][3]));
            }
            mx0 = fmaxf(mx0, __shfl_xor_sync(0xffffffffu, mx0, 1));
            mx0 = fmaxf(mx0, __shfl_xor_sync(0xffffffffu, mx0, 2));
            mx1 = fmaxf(mx1, __shfl_xor_sync(0xffffffffu, mx1, 1));
            mx1 = fmaxf(mx1, __shfl_xor_sync(0xffffffffu, mx1, 2));

            const float mn0 = fmaxf(m0, mx0);
            const float mn1 = fmaxf(m1, mx1);
            const float a0 = __expf(m0 - mn0);
            const float a1 = __expf(m1 - mn1);
            m0 = mn0; m1 = mn1;

            float s0 = 0.f, s1 = 0.f;
#pragma unroll
            for (int nt = 0; nt < 8; ++nt) {
                sacc[nt][0] = __expf(sacc[nt][0] - mn0);
                sacc[nt][1] = __expf(sacc[nt][1] - mn0);
                sacc[nt][2] = __expf(sacc[nt][2] - mn1);
                sacc[nt][3] = __expf(sacc[nt][3] - mn1);
                s0 += sacc[nt][0] + sacc[nt][1];
                s1 += sacc[nt][2] + sacc[nt][3];
            }
            s0 += __shfl_xor_sync(0xffffffffu, s0, 1);
            s0 += __shfl_xor_sync(0xffffffffu, s0, 2);
            s1 += __shfl_xor_sync(0xffffffffu, s1, 1);
            s1 += __shfl_xor_sync(0xffffffffu, s1, 2);
            l0 = l0*a0 + s0;
            l1 = l1*a1 + s1;

#pragma unroll
            for (int nt = 0; nt < 8; ++nt) {
                O[nt][0] *= a0;  O[nt][1] *= a0;
                O[nt][2] *= a1;  O[nt][3] *= a1;
            }

#pragma unroll
            for (int kb = 0; kb < 4; ++kb) {
                const uint32_t pa0 = pack2(sacc[2*kb  ][0], sacc[2*kb  ][1]);
                const uint32_t pa1 = pack2(sacc[2*kb  ][2], sacc[2*kb  ][3]);
                const uint32_t pa2 = pack2(sacc[2*kb+1][0], sacc[2*kb+1][1]);
                const uint32_t pa3 = pack2(sacc[2*kb+1][2], sacc[2*kb+1][3]);
#pragma unroll
                for (int nt = 0; nt < 8; ++nt) {
                    uint32_t b0 = Vsb[(kb*8 + tig    )*VWS + nt*8 + gr];
                    uint32_t b1 = Vsb[(kb*8 + tig + 4)*VWS + nt*8 + gr];
                    mma_f16(O[nt][0], O[nt][1], O[nt][2], O[nt][3],
                            pa0, pa1, pa2, pa3, b0, b1);
                }
            }
        }

        if (more) {
            const int nb = cur ^ 1;
            *(uint4*)&Kw[nb][sr*KWS + sdw    ] = ka;
            *(uint4*)&Kw[nb][sr*KWS + sdw + 4] = kb2;
            uint4 wA = make_uint4(__byte_perm(u0.x, u1.x, 0x5410),
                                  __byte_perm(u0.x, u1.x, 0x7632),
                                  __byte_perm(u0.y, u1.y, 0x5410),
                                  __byte_perm(u0.y, u1.y, 0x7632));
            uint4 wB = make_uint4(__byte_perm(u0.z, u1.z, 0x5410),
                                  __byte_perm(u0.z, u1.z, 0x7632),
                                  __byte_perm(u0.w, u1.w, 0x5410),
                                  __byte_perm(u0.w, u1.w, 0x7632));
            *(uint4*)&Vw[nb][vp*VWS + vdc    ] = wA;
            *(uint4*)&Vw[nb][vp*VWS + vdc + 4] = wB;
        }
        __syncthreads();
    }

    // ---- Epilogue: write O as tgemm<1> A-fragments into g_yf ----
    const int b = bh / NHz;
    const int h = bh % NHz;
    const float inv0 = 1.f / l0;
    const float inv1 = 1.f / l1;
    const int bm24 = ((b << 3) + qb) * NSTG;        // block row of g_yf
    const int swzo = (lane ^ ((lane >> 3) & 3)) * 4;
#pragma unroll
    for (int sh = 0; sh < 2; ++sh) {
#pragma unroll
        for (int ks = 0; ks < 2; ++ks) {
            const int s  = 2*h + sh;
            const int nt = sh*4 + ks*2;
            uint4 w;
            w.x = pack2(O[nt  ][0]*inv0, O[nt  ][1]*inv0);  // a0 (gr,   tig)
            w.y = pack2(O[nt  ][2]*inv1, O[nt  ][3]*inv1);  // a1 (gr+8, tig)
            w.z = pack2(O[nt+1][0]*inv0, O[nt+1][1]*inv0);  // a2 (gr,   tig+4)
            w.w = pack2(O[nt+1][2]*inv1, O[nt+1][3]*inv1);  // a3 (gr+8, tig+4)
            *(uint4*)&gy[((size_t)(bm24 + s))*2048 + (wid*2 + ks)*128 + swzo] = w;
        }
    }
}

// ---------------------------------------------------------------------------
extern "C" void kernel_launch(void* const* d_in, const int* in_sizes, int n_in,
                              void* d_out, int out_size)
{
    (void)in_sizes; (void)n_in; (void)out_size;
    const float* x      = (const float*)d_in[0];
    const float* w_attn = (const float*)d_in[1];
    const float* b_attn = (const float*)d_in[2];
    const float* w_proj = (const float*)d_in[3];
    const float* b_proj = (const float*)d_in[4];
    float* out = (float*)d_out;

    uint32_t *pq, *pk, *pv, *pxf, *pyf, *pwa, *pwp;
    cudaGetSymbolAddress((void**)&pq,  g_qw);
    cudaGetSymbolAddress((void**)&pk,  g_kw);
    cudaGetSymbolAddress((void**)&pv,  g_vw);
    cudaGetSymbolAddress((void**)&pxf, g_xf);
    cudaGetSymbolAddress((void**)&pyf, g_yf);
    cudaGetSymbolAddress((void**)&pwa, g_waf);
    cudaGetSymbolAddress((void**)&pwp, g_wpf);

    const int gemm_smem = GS_WORDS * (int)sizeof(uint32_t);   // 48 KB
    cudaFuncSetAttribute(tgemm_kernel<0>,
                         cudaFuncAttributeMaxDynamicSharedMemorySize, gemm_smem);
    cudaFuncSetAttribute(tgemm_kernel<1>,
                         cudaFuncAttributeMaxDynamicSharedMemorySize, gemm_smem);

    // 0) Pre-pass: fragment-major images
    conv_xf<<<3072, 256>>>(x, pxf);              // 64*24*512 uint4 / 256 = 3072
    conv_wf<<<1728, 256>>>(w_attn, pwa, 3*Cz);   // 18*24*1024 / 256
    conv_wf<<<576,  256>>>(w_proj, pwp, Cz);     // 6*24*1024 / 256

    // 1) QKV = x @ w_attn + b_attn, scatter half2 q/k/v
    {
        dim3 grid(3*Cz/128, Mz/128);   // (18, 64)
        tgemm_kernel<0><<<grid, 256, gemm_smem>>>(pxf, pwa, b_attn, nullptr, 3*Cz);
    }
    // 2) Flash attention -> g_yf (fragment-major)
    {
        dim3 grid(Bz*NHz, Tz/128);
        flash2_kernel<<<grid, 256>>>(pq, pk, pv, pyf);
    }
    // 3) out = y @ w_proj + b_proj (f32 out)
    {
        dim3 grid(Cz/128, Mz/128);     // (6, 64)
        tgemm_kernel<1><<<grid, 256, gemm_smem>>>(pyf, pwp, b_proj, out, Cz);
    }
}